// round 9
// baseline (speedup 1.0000x reference)
#include <cuda_runtime.h>
#include <math.h>

#define BB 4
#define NN 20480
#define KK 16
#define NPTS (BB*NN)   // 81920

typedef unsigned long long ull;
__device__ __forceinline__ ull pk2(float a,float b){ull r;asm("mov.b64 %0,{%1,%2};":"=l"(r):"f"(a),"f"(b));return r;}
__device__ __forceinline__ void up2(ull p,float&a,float&b){asm("mov.b64 {%0,%1},%2;":"=f"(a),"=f"(b):"l"(p));}
__device__ __forceinline__ ull fma2(ull a,ull b,ull c){ull d;asm("fma.rn.f32x2 %0,%1,%2,%3;":"=l"(d):"l"(a),"l"(b),"l"(c));return d;}
__device__ __forceinline__ ull mul2(ull a,ull b){ull d;asm("mul.rn.f32x2 %0,%1,%2;":"=l"(d):"l"(a),"l"(b));return d;}
__device__ __forceinline__ ull add2(ull a,ull b){ull d;asm("add.rn.f32x2 %0,%1,%2;":"=l"(d):"l"(a),"l"(b));return d;}

// ---------------- scratch (device globals, no allocation) ----------------
__device__ float g_featT[NPTS*16];
__device__ float g_feat0[NPTS*16];
__device__ float g_feat1[NPTS*16];
__device__ float g_lrep[(size_t)NPTS*KK*16];
__device__ float g_gdis[NPTS*KK];
__device__ float g_lg[NPTS];
__device__ float g_pool[(size_t)NPTS*32];   // p2m output (32 ch per point)

// preprocessed weights
__device__ float g_wm1[256];
__device__ float g_wlm1p[192];
__device__ float g_wlm2[256];
__device__ __align__(16) float g_p1fcd[2304]; // dup: [o][72]: {wg,wg,wf,wf,pad4, w0,w0,w1,w1,...}
__device__ float g_wp1mt[512];
__device__ __align__(16) float g_p2fcd[2304];
__device__ float g_wp2mt[1024];
__device__ float g_m2t[2048];   // [c][o] c<32 o<64
__device__ float g_sct[1024];   // [c][o] c<16
__device__ float g_m3t[256];    // [c][o] c<4
__device__ float g_m4t[8192];   // [c][o] c<128

// ---------------- prep ----------------------------------------------------
__global__ void k_prep(const float* m1W,const float* m1g,
                       const float* lm1W,const float* lm1g,
                       const float* lm2W,const float* lm2g,
                       const float* p1fcW,
                       const float* p1mW,const float* p1mg,
                       const float* p2fcW,
                       const float* p2mW,const float* p2mg,
                       const float* m2W,const float* m2g,
                       const float* scW,const float* scg,
                       const float* m3W,const float* m3g,
                       const float* m4W,const float* m4g)
{
  int t=threadIdx.x;
  for(int i=t;i<256;i+=256)  g_wm1[i]=m1g[i>>4]*m1W[i];
  for(int i=t;i<192;i+=256){
    int o=i/12,c=i%12;
    g_wlm1p[i]=(c<9)? lm1g[o]*lm1W[o*9+c] : 0.f;
  }
  for(int i=t;i<256;i+=256)  g_wlm2[i]=lm2g[i>>4]*lm2W[i];
  for(int i=t;i<2304;i+=256){
    int o=i/72,c=i%72; float v=0.f;
    if(c<2) v=p1fcW[o*34];
    else if(c<4) v=2.f*p1fcW[o*34+1];
    else if(c>=8) v=p1fcW[o*34+2+((c-8)>>1)];
    g_p1fcd[i]=v;
  }
  for(int i=t;i<512;i+=256){ int c=i>>4,o=i&15; g_wp1mt[i]=p1mg[o]*p1mW[o*32+c]; }
  for(int i=t;i<2304;i+=256){
    int o=i/72,c=i%72; float v=0.f;
    if(c<2) v=p2fcW[o*34];
    else if(c<4) v=2.f*p2fcW[o*34+1];
    else if(c>=8) v=p2fcW[o*34+2+((c-8)>>1)];
    g_p2fcd[i]=v;
  }
  for(int i=t;i<512;i+=256){
    int c=i>>4,j=i&15;
    g_wp2mt[2*i]  =p2mg[j]   *p2mW[j*32+c];
    g_wp2mt[2*i+1]=p2mg[j+16]*p2mW[(j+16)*32+c];
  }
  for(int i=t;i<2048;i+=256){int o=i>>5,c=i&31;  g_m2t[c*64+o]=m2g[o]*m2W[i];}
  for(int i=t;i<1024;i+=256){int o=i>>4,c=i&15;  g_sct[c*64+o]=scg[o]*scW[i];}
  for(int i=t;i<256;i+=256) {int o=i>>2,c=i&3;   g_m3t[c*64+o]=m3g[o]*m3W[i];}
  for(int i=t;i<8192;i+=256){int o=i>>7,c=i&127; g_m4t[c*64+o]=m4g[o]*m4W[i];}
}

// ---------------- kernel A ------------------------------------------------
__global__ void __launch_bounds__(256) kA(const float* __restrict__ feature,
                                          const float* __restrict__ m1b){
  __shared__ __align__(16) float sW[256];
  __shared__ float sb[16];
  int t=threadIdx.x;
  if(t<256) sW[t]=g_wm1[t];
  if(t<16)  sb[t]=m1b[t];
  __syncthreads();
  int p = blockIdx.x*256 + t;
  int b = p/NN, n = p - b*NN;
  float in[16];
  const float* fb = feature + (size_t)b*16*NN + n;
#pragma unroll
  for(int c=0;c<16;c++) in[c]=fb[(size_t)c*NN];
  float4* ft=(float4*)&g_featT[(size_t)p*16];
  ft[0]=make_float4(in[0],in[1],in[2],in[3]);
  ft[1]=make_float4(in[4],in[5],in[6],in[7]);
  ft[2]=make_float4(in[8],in[9],in[10],in[11]);
  ft[3]=make_float4(in[12],in[13],in[14],in[15]);
  float o0[16];
#pragma unroll
  for(int o=0;o<16;o++){
    float a=sb[o];
#pragma unroll
    for(int q=0;q<4;q++){
      float4 w=*(const float4*)&sW[o*16+4*q];
      a+=w.x*in[4*q]+w.y*in[4*q+1]+w.z*in[4*q+2]+w.w*in[4*q+3];
    }
    o0[o]=fmaxf(a,0.f);
  }
  float4* f0=(float4*)&g_feat0[(size_t)p*16];
  f0[0]=make_float4(o0[0],o0[1],o0[2],o0[3]);
  f0[1]=make_float4(o0[4],o0[5],o0[6],o0[7]);
  f0[2]=make_float4(o0[8],o0[9],o0[10],o0[11]);
  f0[3]=make_float4(o0[12],o0[13],o0[14],o0[15]);
}

// ---------------- kernel B-geom: geometry + lm1 -> lrep, gdis, lg ---------
__global__ void __launch_bounds__(256,3) kBg(const float* __restrict__ xyz,
                                             const int* __restrict__ nidx,
                                             const float* __restrict__ lm1b){
  __shared__ __align__(16) float sLW[192];
  __shared__ float sLb[16];
  int t=threadIdx.x;
  for(int i=t;i<192;i+=256) sLW[i]=g_wlm1p[i];
  if(t<16) sLb[t]=lm1b[t];
  __syncthreads();

  int pp=t>>4, k=t&15;
  int p = blockIdx.x*16 + pp;
  int b = p/NN, n = p - b*NN;
  int j = nidx[p*KK+k];
  const float* xb = xyz + (size_t)b*NN*3;
  float Xx=xb[3*n], Xy=xb[3*n+1], Xz=xb[3*n+2];
  float Ax=xb[3*j], Ay=xb[3*j+1], Az=xb[3*j+2];
  float rx=Xx-Ax, ry=Xy-Ay, rz=Xz-Az;
  float rxy2=rx*rx+ry*ry;
  float rdis=sqrtf(rxy2+rz*rz);
  float ralpha=atan2f(ry,rx);
  float rbeta =atan2f(rz,sqrtf(rxy2));
  g_gdis[p*KK+k]=__expf(-rdis);

  float maxd=rdis, sx=Ax, sy=Ay, sz=Az;
#pragma unroll
  for(int m=1;m<16;m<<=1){
    maxd=fmaxf(maxd,__shfl_xor_sync(0xffffffffu,maxd,m));
    sx+=__shfl_xor_sync(0xffffffffu,sx,m);
    sy+=__shfl_xor_sync(0xffffffffu,sy,m);
    sz+=__shfl_xor_sync(0xffffffffu,sz,m);
  }
  float dvx=Xx-sx*0.0625f, dvy=Xy-sy*0.0625f, dvz=Xz-sz*0.0625f;
  float dalpha=atan2f(dvy,dvx);
  float dbeta =atan2f(dvz,sqrtf(dvx*dvx+dvy*dvy));
  if(k==0){
    float gn=sqrtf(Xx*Xx+Xy*Xy+Xz*Xz);
    g_lg[p]=(maxd*maxd*maxd)/(gn*gn*gn);
  }

  float lr[12]={ralpha-dalpha, rbeta-dbeta, rdis, Xx,Xy,Xz, Ax,Ay,Az, 0.f,0.f,0.f};
  float lo[16];
#pragma unroll
  for(int o=0;o<16;o++){
    float a=sLb[o];
#pragma unroll
    for(int q=0;q<3;q++){
      float4 w=*(const float4*)&sLW[o*12+4*q];
      a+=w.x*lr[4*q]+w.y*lr[4*q+1]+w.z*lr[4*q+2]+w.w*lr[4*q+3];
    }
    lo[o]=fmaxf(a,0.f);
  }
  float4* lp=(float4*)&g_lrep[((size_t)p*KK+k)*16];
  lp[0]=make_float4(lo[0],lo[1],lo[2],lo[3]);
  lp[1]=make_float4(lo[4],lo[5],lo[6],lo[7]);
  lp[2]=make_float4(lo[8],lo[9],lo[10],lo[11]);
  lp[3]=make_float4(lo[12],lo[13],lo[14],lo[15]);
}

// ---------------- kernel B-pool: pool1 + p1m, 2 pts/thread, f32x2 ---------
__global__ void __launch_bounds__(256,2) kBp(const int* __restrict__ nidx,
                                             const float* __restrict__ p1mb){
  __shared__ __align__(16) float sFC[2304];
  __shared__ float sPT[512], sPb[16];
  int t=threadIdx.x;
  for(int i=t;i<2304;i+=256) sFC[i]=g_p1fcd[i];
  for(int i=t;i<512;i+=256)  sPT[i]=g_wp1mt[i];
  if(t<16) sPb[t]=p1mb[t];
  __syncthreads();

  int pp=t>>4, k=t&15;
  int pA=blockIdx.x*32+pp;
  int pB=pA+16;
  int bA=pA/NN, bB=pB/NN;
  int jA=nidx[pA*KK+k], jB=nidx[pB*KK+k];

  ull fpack[32];
  // lrep (lm1 output) -> channels 16..31
  {
    const float4* la=(const float4*)&g_lrep[((size_t)pA*KK+k)*16];
    const float4* lb=(const float4*)&g_lrep[((size_t)pB*KK+k)*16];
#pragma unroll
    for(int q=0;q<4;q++){
      float4 u=la[q], v=lb[q];
      fpack[16+4*q  ]=pk2(u.x,v.x);
      fpack[16+4*q+1]=pk2(u.y,v.y);
      fpack[16+4*q+2]=pk2(u.z,v.z);
      fpack[16+4*q+3]=pk2(u.w,v.w);
    }
  }
  // neighbor feat gather -> channels 0..15, fdis
  float adA=0.f, adB=0.f;
  {
    const float4* fjA=(const float4*)&g_feat0[((size_t)bA*NN+jA)*16];
    const float4* fnA=(const float4*)&g_feat0[(size_t)pA*16];
    const float4* fjB=(const float4*)&g_feat0[((size_t)bB*NN+jB)*16];
    const float4* fnB=(const float4*)&g_feat0[(size_t)pB*16];
#pragma unroll
    for(int q=0;q<4;q++){
      float4 a=fjA[q], an=fnA[q], b=fjB[q], bn=fnB[q];
      fpack[4*q  ]=pk2(a.x,b.x);
      fpack[4*q+1]=pk2(a.y,b.y);
      fpack[4*q+2]=pk2(a.z,b.z);
      fpack[4*q+3]=pk2(a.w,b.w);
      adA+=fabsf(an.x-a.x)+fabsf(an.y-a.y)+fabsf(an.z-a.z)+fabsf(an.w-a.w);
      adB+=fabsf(bn.x-b.x)+fabsf(bn.y-b.y)+fabsf(bn.z-b.z)+fabsf(bn.w-b.w);
    }
  }
  ull gpair=pk2(g_gdis[pA*KK+k], g_gdis[pB*KK+k]);
  ull fpair=pk2(__expf(-adA*0.0625f), __expf(-adB*0.0625f));

  float accA=0.f, accB=0.f;
#pragma unroll
  for(int o=0;o<32;o++){
    const float* w=&sFC[o*72];
    ulonglong2 wgf=*(const ulonglong2*)w;        // {wg,wg},{wf,wf}
    ull sA=mul2(wgf.x,gpair);
    ull sB=mul2(wgf.y,fpair);
    const ulonglong2* wr=(const ulonglong2*)(w+8);
#pragma unroll
    for(int q=0;q<16;q++){
      ulonglong2 wp=wr[q];
      sA=fma2(wp.x,fpack[2*q],sA);
      sB=fma2(wp.y,fpack[2*q+1],sB);
    }
    float s0,s1; up2(add2(sA,sB),s0,s1);
    float e0=__expf(s0), e1=__expf(s1);
    float a0,b0; up2(fpack[o],a0,b0);
    float t0=e0*a0, t1=e1*b0;
#pragma unroll
    for(int m=1;m<16;m<<=1){
      e0+=__shfl_xor_sync(0xffffffffu,e0,m);
      t0+=__shfl_xor_sync(0xffffffffu,t0,m);
      e1+=__shfl_xor_sync(0xffffffffu,e1,m);
      t1+=__shfl_xor_sync(0xffffffffu,t1,m);
    }
    float w1=sPT[o*16+k];
    accA+=w1*__fdividef(t0,e0);
    accB+=w1*__fdividef(t1,e1);
  }
  g_feat1[(size_t)pA*16+k]=fmaxf(accA+sPb[k],0.f);
  g_feat1[(size_t)pB*16+k]=fmaxf(accB+sPb[k],0.f);
}

// ---------------- kernel C1: lrep2 + pool2 + p2m, 2 pts/thread, f32x2 -----
__global__ void __launch_bounds__(256,2) kC1(const int* __restrict__ nidx,
                    const float* __restrict__ lm2b, const float* __restrict__ p2mb){
  __shared__ __align__(16) float sL[256];
  __shared__ __align__(16) float sFC[2304];
  __shared__ float2 sPT[512];
  __shared__ float sLb[16], sPb[32];
  int t=threadIdx.x;
  for(int i=t;i<256;i+=256)  sL[i]=g_wlm2[i];
  for(int i=t;i<2304;i+=256) sFC[i]=g_p2fcd[i];
  for(int i=t;i<512;i+=256)  sPT[i]=make_float2(g_wp2mt[2*i],g_wp2mt[2*i+1]);
  if(t<16) sLb[t]=lm2b[t];
  if(t<32) sPb[t]=p2mb[t];
  __syncthreads();

  int pp=t>>4, k=t&15;
  int pA=blockIdx.x*32+pp;
  int pB=pA+16;
  int bA=pA/NN, bB=pB/NN;
  int jA=nidx[pA*KK+k], jB=nidx[pB*KK+k];

  ull fpack[32];
  // lrep2 = relu(lm2 cbr(lrep)) -> channels 16..31
  {
    float lrA[16], lrB[16];
    const float4* la=(const float4*)&g_lrep[((size_t)pA*KK+k)*16];
    const float4* lb=(const float4*)&g_lrep[((size_t)pB*KK+k)*16];
#pragma unroll
    for(int q=0;q<4;q++){
      float4 v=la[q]; lrA[4*q]=v.x; lrA[4*q+1]=v.y; lrA[4*q+2]=v.z; lrA[4*q+3]=v.w;
      float4 u=lb[q]; lrB[4*q]=u.x; lrB[4*q+1]=u.y; lrB[4*q+2]=u.z; lrB[4*q+3]=u.w;
    }
#pragma unroll
    for(int o=0;o<16;o++){
      float a0=sLb[o], a1=a0;
#pragma unroll
      for(int q=0;q<4;q++){
        float4 w=*(const float4*)&sL[o*16+4*q];
        a0+=w.x*lrA[4*q]+w.y*lrA[4*q+1]+w.z*lrA[4*q+2]+w.w*lrA[4*q+3];
        a1+=w.x*lrB[4*q]+w.y*lrB[4*q+1]+w.z*lrB[4*q+2]+w.w*lrB[4*q+3];
      }
      fpack[16+o]=pk2(fmaxf(a0,0.f),fmaxf(a1,0.f));
    }
  }
  // feat1 gather -> channels 0..15, fdis
  float adA=0.f, adB=0.f;
  {
    const float4* fjA=(const float4*)&g_feat1[((size_t)bA*NN+jA)*16];
    const float4* fnA=(const float4*)&g_feat1[(size_t)pA*16];
    const float4* fjB=(const float4*)&g_feat1[((size_t)bB*NN+jB)*16];
    const float4* fnB=(const float4*)&g_feat1[(size_t)pB*16];
#pragma unroll
    for(int q=0;q<4;q++){
      float4 a=fjA[q], an=fnA[q], b=fjB[q], bn=fnB[q];
      fpack[4*q  ]=pk2(a.x,b.x);
      fpack[4*q+1]=pk2(a.y,b.y);
      fpack[4*q+2]=pk2(a.z,b.z);
      fpack[4*q+3]=pk2(a.w,b.w);
      adA+=fabsf(an.x-a.x)+fabsf(an.y-a.y)+fabsf(an.z-a.z)+fabsf(an.w-a.w);
      adB+=fabsf(bn.x-b.x)+fabsf(bn.y-b.y)+fabsf(bn.z-b.z)+fabsf(bn.w-b.w);
    }
  }
  ull gpair=pk2(g_gdis[pA*KK+k], g_gdis[pB*KK+k]);
  ull fpair=pk2(__expf(-adA*0.0625f), __expf(-adB*0.0625f));

  float v0A=0.f,v1A=0.f,v0B=0.f,v1B=0.f;
#pragma unroll
  for(int o=0;o<32;o++){
    const float* w=&sFC[o*72];
    ulonglong2 wgf=*(const ulonglong2*)w;
    ull sA=mul2(wgf.x,gpair);
    ull sB=mul2(wgf.y,fpair);
    const ulonglong2* wr=(const ulonglong2*)(w+8);
#pragma unroll
    for(int q=0;q<16;q++){
      ulonglong2 wp=wr[q];
      sA=fma2(wp.x,fpack[2*q],sA);
      sB=fma2(wp.y,fpack[2*q+1],sB);
    }
    float s0,s1; up2(add2(sA,sB),s0,s1);
    float e0=__expf(s0), e1=__expf(s1);
    float a0,b0; up2(fpack[o],a0,b0);
    float t0=e0*a0, t1=e1*b0;
#pragma unroll
    for(int m=1;m<16;m<<=1){
      e0+=__shfl_xor_sync(0xffffffffu,e0,m);
      t0+=__shfl_xor_sync(0xffffffffu,t0,m);
      e1+=__shfl_xor_sync(0xffffffffu,e1,m);
      t1+=__shfl_xor_sync(0xffffffffu,t1,m);
    }
    float2 wp2=sPT[o*16+k];
    float f0=__fdividef(t0,e0), f1=__fdividef(t1,e1);
    v0A+=wp2.x*f0; v1A+=wp2.y*f0;
    v0B+=wp2.x*f1; v1B+=wp2.y*f1;
  }
  g_pool[(size_t)pA*32+k]   =fmaxf(v0A+sPb[k],0.f);
  g_pool[(size_t)pA*32+16+k]=fmaxf(v1A+sPb[k+16],0.f);
  g_pool[(size_t)pB*32+k]   =fmaxf(v0B+sPb[k],0.f);
  g_pool[(size_t)pB*32+16+k]=fmaxf(v1B+sPb[k+16],0.f);
}

// ---------------- kernel C2: fused m2+sc+m3 -> h -> m4 -> out -------------
__global__ void __launch_bounds__(256) kC2(const float* __restrict__ xyz,
                                           const float* __restrict__ m2b,
                                           const float* __restrict__ scb,
                                           const float* __restrict__ m3b,
                                           const float* __restrict__ m4b,
                                           float* __restrict__ out){
  __shared__ __align__(16) float sW[8192];
  __shared__ __align__(16) float sh[16*132];
  __shared__ __align__(16) float sv[16*32];
  __shared__ float sb[64], sM2b[64], sSCb[64], sM3b[64];
  int t=threadIdx.x;
  for(int i=t;i<8192;i+=256) sW[i]=g_m4t[i];
  if(t<64){ sb[t]=m4b[t]; sM2b[t]=m2b[t]; sSCb[t]=scb[t]; sM3b[t]=m3b[t]; }
  if(t<128){
    float4 v=((const float4*)&g_pool[(size_t)blockIdx.x*16*32])[t];
    ((float4*)sv)[t]=v;
  }
  __syncthreads();

  int pp=t>>4, k=t&15;
  int p=blockIdx.x*16+pp;
  int b=p/NN, n=p-b*NN;
  int o0=4*k;

  const float* vv=&sv[pp*32];
  float4 acc=make_float4(0.f,0.f,0.f,0.f);
#pragma unroll
  for(int c=0;c<32;c++){
    float vc=vv[c];
    float4 w=*(const float4*)&g_m2t[c*64+o0];
    acc.x+=w.x*vc; acc.y+=w.y*vc; acc.z+=w.z*vc; acc.w+=w.w*vc;
  }
  const float* ft=&g_featT[(size_t)p*16];
  float4 asc=make_float4(0.f,0.f,0.f,0.f);
#pragma unroll
  for(int c=0;c<16;c++){
    float fc=ft[c];
    float4 w=*(const float4*)&g_sct[c*64+o0];
    asc.x+=w.x*fc; asc.y+=w.y*fc; asc.z+=w.z*fc; asc.w+=w.w*fc;
  }
  const float* xb=xyz+(size_t)b*NN*3;
  float g3[4]={xb[3*n],xb[3*n+1],xb[3*n+2],g_lg[p]};
  float4 agc=make_float4(0.f,0.f,0.f,0.f);
#pragma unroll
  for(int c=0;c<4;c++){
    float fc=g3[c];
    float4 w=*(const float4*)&g_m3t[c*64+o0];
    agc.x+=w.x*fc; agc.y+=w.y*fc; agc.z+=w.z*fc; agc.w+=w.w*fc;
  }
  float4 hl=make_float4(acc.x+sM2b[o0]+asc.x+sSCb[o0],
                        acc.y+sM2b[o0+1]+asc.y+sSCb[o0+1],
                        acc.z+sM2b[o0+2]+asc.z+sSCb[o0+2],
                        acc.w+sM2b[o0+3]+asc.w+sSCb[o0+3]);
  float4 hh=make_float4(agc.x+sM3b[o0],agc.y+sM3b[o0+1],
                        agc.z+sM3b[o0+2],agc.w+sM3b[o0+3]);
  ((float4*)(sh+pp*132))[k]=hl;
  ((float4*)(sh+pp*132))[16+k]=hh;
  __syncthreads();

  const float4* hb4=(const float4*)&sh[pp*132];
  float4 a4=make_float4(0.f,0.f,0.f,0.f);
#pragma unroll
  for(int c4=0;c4<32;c4++){
    float4 h4=hb4[c4];
    float4 w0=*(const float4*)&sW[(4*c4  )*64+o0];
    float4 w1=*(const float4*)&sW[(4*c4+1)*64+o0];
    float4 w2=*(const float4*)&sW[(4*c4+2)*64+o0];
    float4 w3=*(const float4*)&sW[(4*c4+3)*64+o0];
    a4.x+=w0.x*h4.x+w1.x*h4.y+w2.x*h4.z+w3.x*h4.w;
    a4.y+=w0.y*h4.x+w1.y*h4.y+w2.y*h4.z+w3.y*h4.w;
    a4.z+=w0.z*h4.x+w1.z*h4.y+w2.z*h4.z+w3.z*h4.w;
    a4.w+=w0.w*h4.x+w1.w*h4.y+w2.w*h4.z+w3.w*h4.w;
  }
  size_t base=((size_t)b*64+o0)*NN+n;
  out[base]             =fmaxf(a4.x+sb[o0]  ,0.f);
  out[base+NN]          =fmaxf(a4.y+sb[o0+1],0.f);
  out[base+2*(size_t)NN]=fmaxf(a4.z+sb[o0+2],0.f);
  out[base+3*(size_t)NN]=fmaxf(a4.w+sb[o0+3],0.f);
}

// ---------------- launch ---------------------------------------------------
extern "C" void kernel_launch(void* const* d_in, const int* in_sizes, int n_in,
                              void* d_out, int out_size){
  const float* feature=(const float*)d_in[0];
  const float* xyz    =(const float*)d_in[1];
  const int*   nidx   =(const int*)  d_in[31];
  float* out=(float*)d_out;

  k_prep<<<1,256>>>((const float*)d_in[2],(const float*)d_in[3],
                    (const float*)d_in[5],(const float*)d_in[6],
                    (const float*)d_in[8],(const float*)d_in[9],
                    (const float*)d_in[11],
                    (const float*)d_in[12],(const float*)d_in[13],
                    (const float*)d_in[15],
                    (const float*)d_in[16],(const float*)d_in[17],
                    (const float*)d_in[19],(const float*)d_in[20],
                    (const float*)d_in[22],(const float*)d_in[23],
                    (const float*)d_in[25],(const float*)d_in[26],
                    (const float*)d_in[28],(const float*)d_in[29]);
  kA<<<NPTS/256,256>>>(feature,(const float*)d_in[4]);
  kBg<<<NPTS/16,256>>>(xyz,nidx,(const float*)d_in[7]);
  kBp<<<NPTS/32,256>>>(nidx,(const float*)d_in[14]);
  kC1<<<NPTS/32,256>>>(nidx,(const float*)d_in[10],(const float*)d_in[18]);
  kC2<<<NPTS/16,256>>>(xyz,(const float*)d_in[21],(const float*)d_in[24],
                       (const float*)d_in[27],(const float*)d_in[30],out);
}

// round 13
// speedup vs baseline: 1.2170x; 1.2170x over previous
#include <cuda_runtime.h>
#include <math.h>

#define BB 4
#define NN 20480
#define KK 16
#define NPTS (BB*NN)   // 81920

__host__ __device__ __forceinline__ int bitrev3(int x){
  return ((x&1)<<2)|(x&2)|((x&4)>>2);
}

// ---------------- scratch (device globals, no allocation) ----------------
__device__ float g_featT[NPTS*16];
__device__ float g_feat0[NPTS*16];
__device__ float g_feat1[NPTS*16];
__device__ float g_lrep[(size_t)NPTS*KK*16];
__device__ float g_gdis[NPTS*KK];
__device__ float g_lg[NPTS];
__device__ float g_pool[(size_t)NPTS*32];   // p2m output (32 ch per point)

// preprocessed weights
__device__ float g_wm1[256];
__device__ float g_wlm1p[192];
__device__ float g_wlm2[256];
__device__ float g_p1fc[1152];
__device__ float g_wp1mg[768];   // [blk4][k16][12] bit-reversed gather order (8 real)
__device__ float g_p2fc[1152];
__device__ float g_wp2mg[1280];  // [blk4][k16][20] float2 pairs (8 real)
__device__ float g_m2t[2048];   // [c][o] c<32 o<64
__device__ float g_sct[1024];   // [c][o] c<16
__device__ float g_m3t[256];    // [c][o] c<4
__device__ float g_m4t[8192];   // [c][o] c<128

// ---------------- prep ----------------------------------------------------
__global__ void k_prep(const float* m1W,const float* m1g,
                       const float* lm1W,const float* lm1g,
                       const float* lm2W,const float* lm2g,
                       const float* p1fcW,
                       const float* p1mW,const float* p1mg,
                       const float* p2fcW,
                       const float* p2mW,const float* p2mg,
                       const float* m2W,const float* m2g,
                       const float* scW,const float* scg,
                       const float* m3W,const float* m3g,
                       const float* m4W,const float* m4g)
{
  int t=threadIdx.x;
  for(int i=t;i<256;i+=256)  g_wm1[i]=m1g[i>>4]*m1W[i];
  for(int i=t;i<192;i+=256){
    int o=i/12,c=i%12;
    g_wlm1p[i]=(c<9)? lm1g[o]*lm1W[o*9+c] : 0.f;
  }
  for(int i=t;i<256;i+=256)  g_wlm2[i]=lm2g[i>>4]*lm2W[i];
  for(int i=t;i<1152;i+=256){
    int o=i/36,c=i%36; float v=0.f;
    if(c==0) v=p1fcW[o*34];
    else if(c==1) v=2.f*p1fcW[o*34+1];
    else if(c>=4) v=p1fcW[o*34+2+(c-4)];
    g_p1fc[i]=v;
  }
  // p1m weights, gather order: [blk][k][i<12] = g*W[k][blk*8+bitrev3((k^i)&7)], pad 4
  for(int i=t;i<768;i+=256){
    int blk=i/192, r=i%192, k=r/12, ii=r%12;
    float v=0.f;
    if(ii<8){ int c=blk*8+bitrev3((k^ii)&7); v=p1mg[k]*p1mW[k*32+c]; }
    g_wp1mg[i]=v;
  }
  for(int i=t;i<1152;i+=256){
    int o=i/36,c=i%36; float v=0.f;
    if(c==0) v=p2fcW[o*34];
    else if(c==1) v=2.f*p2fcW[o*34+1];
    else if(c>=4) v=p2fcW[o*34+2+(c-4)];
    g_p2fc[i]=v;
  }
  // p2m weights, gather order float2: [blk][k][i] = {g*W[k][c], g*W[k+16][c]}
  for(int i=t;i<640;i+=256){
    int blk=i/160, r=i%160, k=r/10, ii=r%10;
    float a=0.f,b=0.f;
    if(ii<8){
      int c=blk*8+bitrev3((k^ii)&7);
      a=p2mg[k]   *p2mW[k*32+c];
      b=p2mg[k+16]*p2mW[(k+16)*32+c];
    }
    g_wp2mg[2*i]=a; g_wp2mg[2*i+1]=b;
  }
  for(int i=t;i<2048;i+=256){int o=i>>5,c=i&31;  g_m2t[c*64+o]=m2g[o]*m2W[i];}
  for(int i=t;i<1024;i+=256){int o=i>>4,c=i&15;  g_sct[c*64+o]=scg[o]*scW[i];}
  for(int i=t;i<256;i+=256) {int o=i>>2,c=i&3;   g_m3t[c*64+o]=m3g[o]*m3W[i];}
  for(int i=t;i<8192;i+=256){int o=i>>7,c=i&127; g_m4t[c*64+o]=m4g[o]*m4W[i];}
}

// ---------------- kernel A ------------------------------------------------
__global__ void __launch_bounds__(256) kA(const float* __restrict__ feature,
                                          const float* __restrict__ m1b){
  __shared__ __align__(16) float sW[256];
  __shared__ float sb[16];
  int t=threadIdx.x;
  if(t<256) sW[t]=g_wm1[t];
  if(t<16)  sb[t]=m1b[t];
  __syncthreads();
  int p = blockIdx.x*256 + t;
  int b = p/NN, n = p - b*NN;
  float in[16];
  const float* fb = feature + (size_t)b*16*NN + n;
#pragma unroll
  for(int c=0;c<16;c++) in[c]=fb[(size_t)c*NN];
  float4* ft=(float4*)&g_featT[(size_t)p*16];
  ft[0]=make_float4(in[0],in[1],in[2],in[3]);
  ft[1]=make_float4(in[4],in[5],in[6],in[7]);
  ft[2]=make_float4(in[8],in[9],in[10],in[11]);
  ft[3]=make_float4(in[12],in[13],in[14],in[15]);
  float o0[16];
#pragma unroll
  for(int o=0;o<16;o++){
    float a=sb[o];
#pragma unroll
    for(int q=0;q<4;q++){
      float4 w=*(const float4*)&sW[o*16+4*q];
      a+=w.x*in[4*q]+w.y*in[4*q+1]+w.z*in[4*q+2]+w.w*in[4*q+3];
    }
    o0[o]=fmaxf(a,0.f);
  }
  float4* f0=(float4*)&g_feat0[(size_t)p*16];
  f0[0]=make_float4(o0[0],o0[1],o0[2],o0[3]);
  f0[1]=make_float4(o0[4],o0[5],o0[6],o0[7]);
  f0[2]=make_float4(o0[8],o0[9],o0[10],o0[11]);
  f0[3]=make_float4(o0[12],o0[13],o0[14],o0[15]);
}

// ---------------- kernel B: geometry + lrep + pool1 + p1m -> feat1 --------
__global__ void __launch_bounds__(256,3) kB(const float* __restrict__ xyz,
                                            const int* __restrict__ nidx,
                                            const float* __restrict__ lm1b,
                                            const float* __restrict__ p1mb){
  __shared__ __align__(16) float sLW[192];
  __shared__ __align__(16) float sFC[1152];
  __shared__ __align__(16) float sPT[768];
  __shared__ float sLb[16], sPb[16];
  int t=threadIdx.x;
  for(int i=t;i<192;i+=256)  sLW[i]=g_wlm1p[i];
  for(int i=t;i<1152;i+=256) sFC[i]=g_p1fc[i];
  for(int i=t;i<768;i+=256)  sPT[i]=g_wp1mg[i];
  if(t<16){ sLb[t]=lm1b[t]; sPb[t]=p1mb[t]; }
  __syncthreads();

  int pp=t>>4, k=t&15;
  int p = blockIdx.x*16 + pp;
  int b = p/NN, n = p - b*NN;
  int j = nidx[p*KK+k];
  const float* xb = xyz + (size_t)b*NN*3;
  float Xx=xb[3*n], Xy=xb[3*n+1], Xz=xb[3*n+2];
  float Ax=xb[3*j], Ay=xb[3*j+1], Az=xb[3*j+2];
  float rx=Xx-Ax, ry=Xy-Ay, rz=Xz-Az;
  float rxy2=rx*rx+ry*ry;
  float rdis=sqrtf(rxy2+rz*rz);
  float ralpha=atan2f(ry,rx);
  float rbeta =atan2f(rz,sqrtf(rxy2));
  float gdis=__expf(-rdis);
  g_gdis[p*KK+k]=gdis;

  float maxd=rdis, sx=Ax, sy=Ay, sz=Az;
#pragma unroll
  for(int m=1;m<16;m<<=1){
    maxd=fmaxf(maxd,__shfl_xor_sync(0xffffffffu,maxd,m));
    sx+=__shfl_xor_sync(0xffffffffu,sx,m);
    sy+=__shfl_xor_sync(0xffffffffu,sy,m);
    sz+=__shfl_xor_sync(0xffffffffu,sz,m);
  }
  float dvx=Xx-sx*0.0625f, dvy=Xy-sy*0.0625f, dvz=Xz-sz*0.0625f;
  float dalpha=atan2f(dvy,dvx);
  float dbeta =atan2f(dvz,sqrtf(dvx*dvx+dvy*dvy));
  if(k==0){
    float gn=sqrtf(Xx*Xx+Xy*Xy+Xz*Xz);
    g_lg[p]=(maxd*maxd*maxd)/(gn*gn*gn);
  }

  float lr[12]={ralpha-dalpha, rbeta-dbeta, rdis, Xx,Xy,Xz, Ax,Ay,Az, 0.f,0.f,0.f};
  float fcat[32];
#pragma unroll
  for(int o=0;o<16;o++){
    float a=sLb[o];
#pragma unroll
    for(int q=0;q<3;q++){
      float4 w=*(const float4*)&sLW[o*12+4*q];
      a+=w.x*lr[4*q]+w.y*lr[4*q+1]+w.z*lr[4*q+2]+w.w*lr[4*q+3];
    }
    fcat[16+o]=fmaxf(a,0.f);
  }
  float4* lp=(float4*)&g_lrep[((size_t)p*KK+k)*16];
  lp[0]=make_float4(fcat[16],fcat[17],fcat[18],fcat[19]);
  lp[1]=make_float4(fcat[20],fcat[21],fcat[22],fcat[23]);
  lp[2]=make_float4(fcat[24],fcat[25],fcat[26],fcat[27]);
  lp[3]=make_float4(fcat[28],fcat[29],fcat[30],fcat[31]);

  const float4* fj4=(const float4*)&g_feat0[((size_t)b*NN+j)*16];
  const float4* fn4=(const float4*)&g_feat0[(size_t)p*16];
  float ad=0.f;
#pragma unroll
  for(int q=0;q<4;q++){
    float4 v=fj4[q], u=fn4[q];
    fcat[4*q]=v.x; fcat[4*q+1]=v.y; fcat[4*q+2]=v.z; fcat[4*q+3]=v.w;
    ad+=fabsf(u.x-v.x)+fabsf(u.y-v.y)+fabsf(u.z-v.z)+fabsf(u.w-v.w);
  }
  float fdis=__expf(-ad*0.0625f);

  float acc=0.f;
#pragma unroll
  for(int blk=0;blk<4;blk++){
    float ev[8], tv[8];
#pragma unroll
    for(int o=0;o<8;o++){
      int ch=blk*8+o;
      const float* w=&sFC[ch*36];
      float2 wgf=*(const float2*)w;
      float s=wgf.x*gdis+wgf.y*fdis;
#pragma unroll
      for(int q=0;q<8;q++){
        float4 wc=*(const float4*)(w+4+4*q);
        s+=wc.x*fcat[4*q]+wc.y*fcat[4*q+1]+wc.z*fcat[4*q+2]+wc.w*fcat[4*q+3];
      }
      float e=__expf(s);
      ev[o]=e; tv[o]=e*fcat[ch];
    }
    // reduce-scatter over the 16-lane group
#pragma unroll
    for(int jj=0;jj<3;jj++){
      int m=1<<jj, half=4>>jj;
      bool hi=(k>>jj)&1;
#pragma unroll
      for(int i=0;i<half;i++){
        float se=hi?ev[i]:ev[i+half];
        float st=hi?tv[i]:tv[i+half];
        float re=__shfl_xor_sync(0xffffffffu,se,m);
        float rt=__shfl_xor_sync(0xffffffffu,st,m);
        ev[i]=(hi?ev[i+half]:ev[i])+re;
        tv[i]=(hi?tv[i+half]:tv[i])+rt;
      }
    }
    ev[0]+=__shfl_xor_sync(0xffffffffu,ev[0],8);
    tv[0]+=__shfl_xor_sync(0xffffffffu,tv[0],8);
    float g[8];
    g[0]=__fdividef(tv[0],ev[0]);
#pragma unroll
    for(int jj=0;jj<3;jj++){
      int m=1<<jj;
#pragma unroll
      for(int i=0;i<m;i++) g[m+i]=__shfl_xor_sync(0xffffffffu,g[i],m);
    }
    const float* wg=&sPT[blk*192+k*12];
    float4 w0=*(const float4*)wg, w1=*(const float4*)(wg+4);
    acc+=w0.x*g[0]+w0.y*g[1]+w0.z*g[2]+w0.w*g[3]
        +w1.x*g[4]+w1.y*g[5]+w1.z*g[6]+w1.w*g[7];
  }
  g_feat1[(size_t)p*16+k]=fmaxf(acc+sPb[k],0.f);
}

// gather neighbor feature + fdis
__device__ __forceinline__ float fgather(const float* __restrict__ fjp,
                                         const float* __restrict__ fnp,
                                         float* fcat){
  const float4* fj4=(const float4*)fjp;
  const float4* fn4=(const float4*)fnp;
  float ad=0.f;
#pragma unroll
  for(int q=0;q<4;q++){
    float4 v=fj4[q], u=fn4[q];
    fcat[4*q]=v.x; fcat[4*q+1]=v.y; fcat[4*q+2]=v.z; fcat[4*q+3]=v.w;
    ad+=fabsf(u.x-v.x)+fabsf(u.y-v.y)+fabsf(u.z-v.z)+fabsf(u.w-v.w);
  }
  return __expf(-ad*0.0625f);
}

// ---------------- kernel C1: pool-only, 2 points per thread ---------------
__global__ void __launch_bounds__(256,2) kC1(const int* __restrict__ nidx,
                    const float* __restrict__ lm2b, const float* __restrict__ p2mb){
  __shared__ __align__(16) float sL[256];
  __shared__ __align__(16) float sFC[1152];
  __shared__ __align__(16) float sPT[1280];
  __shared__ float sLb[16], sPb[32];
  int t=threadIdx.x;
  for(int i=t;i<256;i+=256)  sL[i]=g_wlm2[i];
  for(int i=t;i<1152;i+=256) sFC[i]=g_p2fc[i];
  for(int i=t;i<1280;i+=256) sPT[i]=g_wp2mg[i];
  if(t<16) sLb[t]=lm2b[t];
  if(t<32) sPb[t]=p2mb[t];
  __syncthreads();

  int pp=t>>4, k=t&15;
  int pA=blockIdx.x*32+pp;
  int pB=pA+16;
  int bA=pA/NN, bB=pB/NN;
  int jA=nidx[pA*KK+k], jB=nidx[pB*KK+k];

  float fcatA[32], fcatB[32];
  // lrep2 = relu(lm2 cbr(lrep)) for both points
  {
    float lrA[16], lrB[16];
    const float4* la=(const float4*)&g_lrep[((size_t)pA*KK+k)*16];
    const float4* lb=(const float4*)&g_lrep[((size_t)pB*KK+k)*16];
#pragma unroll
    for(int q=0;q<4;q++){
      float4 v=la[q]; lrA[4*q]=v.x; lrA[4*q+1]=v.y; lrA[4*q+2]=v.z; lrA[4*q+3]=v.w;
      float4 u=lb[q]; lrB[4*q]=u.x; lrB[4*q+1]=u.y; lrB[4*q+2]=u.z; lrB[4*q+3]=u.w;
    }
#pragma unroll
    for(int o=0;o<16;o++){
      float a0=sLb[o], a1=a0;
#pragma unroll
      for(int q=0;q<4;q++){
        float4 w=*(const float4*)&sL[o*16+4*q];
        a0+=w.x*lrA[4*q]+w.y*lrA[4*q+1]+w.z*lrA[4*q+2]+w.w*lrA[4*q+3];
        a1+=w.x*lrB[4*q]+w.y*lrB[4*q+1]+w.z*lrB[4*q+2]+w.w*lrB[4*q+3];
      }
      fcatA[16+o]=fmaxf(a0,0.f);
      fcatB[16+o]=fmaxf(a1,0.f);
    }
  }
  float fdisA=fgather(&g_feat1[((size_t)bA*NN+jA)*16],&g_feat1[(size_t)pA*16],fcatA);
  float fdisB=fgather(&g_feat1[((size_t)bB*NN+jB)*16],&g_feat1[(size_t)pB*16],fcatB);
  float gdisA=g_gdis[pA*KK+k];
  float gdisB=g_gdis[pB*KK+k];

  float v0A=0.f,v1A=0.f,v0B=0.f,v1B=0.f;
#pragma unroll
  for(int blk=0;blk<4;blk++){
    float evA[8],tvA[8],evB[8],tvB[8];
#pragma unroll
    for(int o=0;o<8;o++){
      int ch=blk*8+o;
      const float* w=&sFC[ch*36];
      float2 wgf=*(const float2*)w;
      float s0=wgf.x*gdisA+wgf.y*fdisA;
      float s1=wgf.x*gdisB+wgf.y*fdisB;
#pragma unroll
      for(int q=0;q<8;q++){
        float4 wc=*(const float4*)(w+4+4*q);
        s0+=wc.x*fcatA[4*q]+wc.y*fcatA[4*q+1]+wc.z*fcatA[4*q+2]+wc.w*fcatA[4*q+3];
        s1+=wc.x*fcatB[4*q]+wc.y*fcatB[4*q+1]+wc.z*fcatB[4*q+2]+wc.w*fcatB[4*q+3];
      }
      float e0=__expf(s0), e1=__expf(s1);
      evA[o]=e0; tvA[o]=e0*fcatA[ch];
      evB[o]=e1; tvB[o]=e1*fcatB[ch];
    }
#pragma unroll
    for(int jj=0;jj<3;jj++){
      int m=1<<jj, half=4>>jj;
      bool hi=(k>>jj)&1;
#pragma unroll
      for(int i=0;i<half;i++){
        float sa=hi?evA[i]:evA[i+half];
        float ta=hi?tvA[i]:tvA[i+half];
        float sb2=hi?evB[i]:evB[i+half];
        float tb=hi?tvB[i]:tvB[i+half];
        float ra=__shfl_xor_sync(0xffffffffu,sa,m);
        float qa=__shfl_xor_sync(0xffffffffu,ta,m);
        float rb=__shfl_xor_sync(0xffffffffu,sb2,m);
        float qb=__shfl_xor_sync(0xffffffffu,tb,m);
        evA[i]=(hi?evA[i+half]:evA[i])+ra;
        tvA[i]=(hi?tvA[i+half]:tvA[i])+qa;
        evB[i]=(hi?evB[i+half]:evB[i])+rb;
        tvB[i]=(hi?tvB[i+half]:tvB[i])+qb;
      }
    }
    evA[0]+=__shfl_xor_sync(0xffffffffu,evA[0],8);
    tvA[0]+=__shfl_xor_sync(0xffffffffu,tvA[0],8);
    evB[0]+=__shfl_xor_sync(0xffffffffu,evB[0],8);
    tvB[0]+=__shfl_xor_sync(0xffffffffu,tvB[0],8);
    float gA[8], gB[8];
    gA[0]=__fdividef(tvA[0],evA[0]);
    gB[0]=__fdividef(tvB[0],evB[0]);
#pragma unroll
    for(int jj=0;jj<3;jj++){
      int m=1<<jj;
#pragma unroll
      for(int i=0;i<m;i++){
        gA[m+i]=__shfl_xor_sync(0xffffffffu,gA[i],m);
        gB[m+i]=__shfl_xor_sync(0xffffffffu,gB[i],m);
      }
    }
    const float* wg=&sPT[blk*320+k*20];
#pragma unroll
    for(int i2=0;i2<4;i2++){
      float4 wv=*(const float4*)&wg[4*i2];   // {v0w,v1w} for channels 2*i2, 2*i2+1
      float ga=gA[2*i2], gb=gA[2*i2+1];
      v0A+=wv.x*ga+wv.z*gb; v1A+=wv.y*ga+wv.w*gb;
      float ha=gB[2*i2], hb=gB[2*i2+1];
      v0B+=wv.x*ha+wv.z*hb; v1B+=wv.y*ha+wv.w*hb;
    }
  }
  g_pool[(size_t)pA*32+k]   =fmaxf(v0A+sPb[k],0.f);
  g_pool[(size_t)pA*32+16+k]=fmaxf(v1A+sPb[k+16],0.f);
  g_pool[(size_t)pB*32+k]   =fmaxf(v0B+sPb[k],0.f);
  g_pool[(size_t)pB*32+16+k]=fmaxf(v1B+sPb[k+16],0.f);
}

// ---------------- kernel C2: fused m2+sc+m3 -> h -> m4 -> out -------------
__global__ void __launch_bounds__(256) kC2(const float* __restrict__ xyz,
                                           const float* __restrict__ m2b,
                                           const float* __restrict__ scb,
                                           const float* __restrict__ m3b,
                                           const float* __restrict__ m4b,
                                           float* __restrict__ out){
  __shared__ __align__(16) float sW[8192];
  __shared__ __align__(16) float sh[16*132];
  __shared__ __align__(16) float sv[16*32];
  __shared__ float sb[64], sM2b[64], sSCb[64], sM3b[64];
  int t=threadIdx.x;
  for(int i=t;i<8192;i+=256) sW[i]=g_m4t[i];
  if(t<64){ sb[t]=m4b[t]; sM2b[t]=m2b[t]; sSCb[t]=scb[t]; sM3b[t]=m3b[t]; }
  if(t<128){
    float4 v=((const float4*)&g_pool[(size_t)blockIdx.x*16*32])[t];
    ((float4*)sv)[t]=v;
  }
  __syncthreads();

  int pp=t>>4, k=t&15;
  int p=blockIdx.x*16+pp;
  int b=p/NN, n=p-b*NN;
  int o0=4*k;

  const float* vv=&sv[pp*32];
  float4 acc=make_float4(0.f,0.f,0.f,0.f);
#pragma unroll
  for(int c=0;c<32;c++){
    float vc=vv[c];
    float4 w=*(const float4*)&g_m2t[c*64+o0];
    acc.x+=w.x*vc; acc.y+=w.y*vc; acc.z+=w.z*vc; acc.w+=w.w*vc;
  }
  const float* ft=&g_featT[(size_t)p*16];
  float4 asc=make_float4(0.f,0.f,0.f,0.f);
#pragma unroll
  for(int c=0;c<16;c++){
    float fc=ft[c];
    float4 w=*(const float4*)&g_sct[c*64+o0];
    asc.x+=w.x*fc; asc.y+=w.y*fc; asc.z+=w.z*fc; asc.w+=w.w*fc;
  }
  const float* xb=xyz+(size_t)b*NN*3;
  float g3[4]={xb[3*n],xb[3*n+1],xb[3*n+2],g_lg[p]};
  float4 agc=make_float4(0.f,0.f,0.f,0.f);
#pragma unroll
  for(int c=0;c<4;c++){
    float fc=g3[c];
    float4 w=*(const float4*)&g_m3t[c*64+o0];
    agc.x+=w.x*fc; agc.y+=w.y*fc; agc.z+=w.z*fc; agc.w+=w.w*fc;
  }
  float4 hl=make_float4(acc.x+sM2b[o0]+asc.x+sSCb[o0],
                        acc.y+sM2b[o0+1]+asc.y+sSCb[o0+1],
                        acc.z+sM2b[o0+2]+asc.z+sSCb[o0+2],
                        acc.w+sM2b[o0+3]+asc.w+sSCb[o0+3]);
  float4 hh=make_float4(agc.x+sM3b[o0],agc.y+sM3b[o0+1],
                        agc.z+sM3b[o0+2],agc.w+sM3b[o0+3]);
  ((float4*)(sh+pp*132))[k]=hl;
  ((float4*)(sh+pp*132))[16+k]=hh;
  __syncthreads();

  const float4* hb4=(const float4*)&sh[pp*132];
  float4 a4=make_float4(0.f,0.f,0.f,0.f);
#pragma unroll
  for(int c4=0;c4<32;c4++){
    float4 h4=hb4[c4];
    float4 w0=*(const float4*)&sW[(4*c4  )*64+o0];
    float4 w1=*(const float4*)&sW[(4*c4+1)*64+o0];
    float4 w2=*(const float4*)&sW[(4*c4+2)*64+o0];
    float4 w3=*(const float4*)&sW[(4*c4+3)*64+o0];
    a4.x+=w0.x*h4.x+w1.x*h4.y+w2.x*h4.z+w3.x*h4.w;
    a4.y+=w0.y*h4.x+w1.y*h4.y+w2.y*h4.z+w3.y*h4.w;
    a4.z+=w0.z*h4.x+w1.z*h4.y+w2.z*h4.z+w3.z*h4.w;
    a4.w+=w0.w*h4.x+w1.w*h4.y+w2.w*h4.z+w3.w*h4.w;
  }
  size_t base=((size_t)b*64+o0)*NN+n;
  out[base]             =fmaxf(a4.x+sb[o0]  ,0.f);
  out[base+NN]          =fmaxf(a4.y+sb[o0+1],0.f);
  out[base+2*(size_t)NN]=fmaxf(a4.z+sb[o0+2],0.f);
  out[base+3*(size_t)NN]=fmaxf(a4.w+sb[o0+3],0.f);
}

// ---------------- launch ---------------------------------------------------
extern "C" void kernel_launch(void* const* d_in, const int* in_sizes, int n_in,
                              void* d_out, int out_size){
  const float* feature=(const float*)d_in[0];
  const float* xyz    =(const float*)d_in[1];
  const int*   nidx   =(const int*)  d_in[31];
  float* out=(float*)d_out;

  k_prep<<<1,256>>>((const float*)d_in[2],(const float*)d_in[3],
                    (const float*)d_in[5],(const float*)d_in[6],
                    (const float*)d_in[8],(const float*)d_in[9],
                    (const float*)d_in[11],
                    (const float*)d_in[12],(const float*)d_in[13],
                    (const float*)d_in[15],
                    (const float*)d_in[16],(const float*)d_in[17],
                    (const float*)d_in[19],(const float*)d_in[20],
                    (const float*)d_in[22],(const float*)d_in[23],
                    (const float*)d_in[25],(const float*)d_in[26],
                    (const float*)d_in[28],(const float*)d_in[29]);
  kA<<<NPTS/256,256>>>(feature,(const float*)d_in[4]);
  kB<<<NPTS/16,256>>>(xyz,nidx,(const float*)d_in[7],(const float*)d_in[14]);
  kC1<<<NPTS/32,256>>>(nidx,(const float*)d_in[10],(const float*)d_in[18]);
  kC2<<<NPTS/16,256>>>(xyz,(const float*)d_in[21],(const float*)d_in[24],
                       (const float*)d_in[27],(const float*)d_in[30],out);
}

// round 14
// speedup vs baseline: 1.2212x; 1.0035x over previous
#include <cuda_runtime.h>
#include <math.h>

#define BB 4
#define NN 20480
#define KK 16
#define NPTS (BB*NN)   // 81920

__host__ __device__ __forceinline__ int bitrev3(int x){
  return ((x&1)<<2)|(x&2)|((x&4)>>2);
}

// ---------------- scratch (device globals, no allocation) ----------------
__device__ float g_featT[NPTS*16];
__device__ float g_feat0[NPTS*16];
__device__ float g_feat1[NPTS*16];
__device__ float g_lrep[(size_t)NPTS*KK*16];
__device__ float g_gdis[NPTS*KK];
__device__ float g_lg[NPTS];
__device__ float g_pool[(size_t)NPTS*32];   // p2m output (32 ch per point)

// preprocessed weights
__device__ float g_wm1[256];
__device__ float g_wlm1p[192];
__device__ float g_wlm2[256];
__device__ float g_p1fc[1152];
__device__ float g_wp1mg[768];   // [blk4][k16][12] bit-reversed gather order (8 real)
__device__ float g_p2fc[1152];
__device__ float g_wp2mg[1280];  // [blk4][k16][20] float2 pairs (8 real)
__device__ float g_m2t[2048];   // [c][o] c<32 o<64
__device__ float g_sct[1024];   // [c][o] c<16
__device__ float g_m3t[256];    // [c][o] c<4
__device__ float g_m4t[8192];   // [c][o] c<128

// ---------------- prep ----------------------------------------------------
__global__ void k_prep(const float* m1W,const float* m1g,
                       const float* lm1W,const float* lm1g,
                       const float* lm2W,const float* lm2g,
                       const float* p1fcW,
                       const float* p1mW,const float* p1mg,
                       const float* p2fcW,
                       const float* p2mW,const float* p2mg,
                       const float* m2W,const float* m2g,
                       const float* scW,const float* scg,
                       const float* m3W,const float* m3g,
                       const float* m4W,const float* m4g)
{
  int t=threadIdx.x;
  for(int i=t;i<256;i+=256)  g_wm1[i]=m1g[i>>4]*m1W[i];
  for(int i=t;i<192;i+=256){
    int o=i/12,c=i%12;
    g_wlm1p[i]=(c<9)? lm1g[o]*lm1W[o*9+c] : 0.f;
  }
  for(int i=t;i<256;i+=256)  g_wlm2[i]=lm2g[i>>4]*lm2W[i];
  for(int i=t;i<1152;i+=256){
    int o=i/36,c=i%36; float v=0.f;
    if(c==0) v=p1fcW[o*34];
    else if(c==1) v=2.f*p1fcW[o*34+1];
    else if(c>=4) v=p1fcW[o*34+2+(c-4)];
    g_p1fc[i]=v;
  }
  // p1m weights, gather order: [blk][k][i<12] = g*W[k][blk*8+bitrev3((k^i)&7)], pad 4
  for(int i=t;i<768;i+=256){
    int blk=i/192, r=i%192, k=r/12, ii=r%12;
    float v=0.f;
    if(ii<8){ int c=blk*8+bitrev3((k^ii)&7); v=p1mg[k]*p1mW[k*32+c]; }
    g_wp1mg[i]=v;
  }
  for(int i=t;i<1152;i+=256){
    int o=i/36,c=i%36; float v=0.f;
    if(c==0) v=p2fcW[o*34];
    else if(c==1) v=2.f*p2fcW[o*34+1];
    else if(c>=4) v=p2fcW[o*34+2+(c-4)];
    g_p2fc[i]=v;
  }
  // p2m weights, gather order float2: [blk][k][i] = {g*W[k][c], g*W[k+16][c]}
  for(int i=t;i<640;i+=256){
    int blk=i/160, r=i%160, k=r/10, ii=r%10;
    float a=0.f,b=0.f;
    if(ii<8){
      int c=blk*8+bitrev3((k^ii)&7);
      a=p2mg[k]   *p2mW[k*32+c];
      b=p2mg[k+16]*p2mW[(k+16)*32+c];
    }
    g_wp2mg[2*i]=a; g_wp2mg[2*i+1]=b;
  }
  for(int i=t;i<2048;i+=256){int o=i>>5,c=i&31;  g_m2t[c*64+o]=m2g[o]*m2W[i];}
  for(int i=t;i<1024;i+=256){int o=i>>4,c=i&15;  g_sct[c*64+o]=scg[o]*scW[i];}
  for(int i=t;i<256;i+=256) {int o=i>>2,c=i&3;   g_m3t[c*64+o]=m3g[o]*m3W[i];}
  for(int i=t;i<8192;i+=256){int o=i>>7,c=i&127; g_m4t[c*64+o]=m4g[o]*m4W[i];}
}

// ---------------- kernel A ------------------------------------------------
__global__ void __launch_bounds__(256) kA(const float* __restrict__ feature,
                                          const float* __restrict__ m1b){
  __shared__ __align__(16) float sW[256];
  __shared__ float sb[16];
  int t=threadIdx.x;
  if(t<256) sW[t]=g_wm1[t];
  if(t<16)  sb[t]=m1b[t];
  __syncthreads();
  int p = blockIdx.x*256 + t;
  int b = p/NN, n = p - b*NN;
  float in[16];
  const float* fb = feature + (size_t)b*16*NN + n;
#pragma unroll
  for(int c=0;c<16;c++) in[c]=fb[(size_t)c*NN];
  float4* ft=(float4*)&g_featT[(size_t)p*16];
  ft[0]=make_float4(in[0],in[1],in[2],in[3]);
  ft[1]=make_float4(in[4],in[5],in[6],in[7]);
  ft[2]=make_float4(in[8],in[9],in[10],in[11]);
  ft[3]=make_float4(in[12],in[13],in[14],in[15]);
  float o0[16];
#pragma unroll
  for(int o=0;o<16;o++){
    float a=sb[o];
#pragma unroll
    for(int q=0;q<4;q++){
      float4 w=*(const float4*)&sW[o*16+4*q];
      a+=w.x*in[4*q]+w.y*in[4*q+1]+w.z*in[4*q+2]+w.w*in[4*q+3];
    }
    o0[o]=fmaxf(a,0.f);
  }
  float4* f0=(float4*)&g_feat0[(size_t)p*16];
  f0[0]=make_float4(o0[0],o0[1],o0[2],o0[3]);
  f0[1]=make_float4(o0[4],o0[5],o0[6],o0[7]);
  f0[2]=make_float4(o0[8],o0[9],o0[10],o0[11]);
  f0[3]=make_float4(o0[12],o0[13],o0[14],o0[15]);
}

// ---------------- kernel B-geom: geometry + lm1 -> lrep, gdis, lg ---------
__global__ void __launch_bounds__(256,3) kBg(const float* __restrict__ xyz,
                                             const int* __restrict__ nidx,
                                             const float* __restrict__ lm1b){
  __shared__ __align__(16) float sLW[192];
  __shared__ float sLb[16];
  int t=threadIdx.x;
  for(int i=t;i<192;i+=256) sLW[i]=g_wlm1p[i];
  if(t<16) sLb[t]=lm1b[t];
  __syncthreads();

  int pp=t>>4, k=t&15;
  int p = blockIdx.x*16 + pp;
  int b = p/NN, n = p - b*NN;
  int j = nidx[p*KK+k];
  const float* xb = xyz + (size_t)b*NN*3;
  float Xx=xb[3*n], Xy=xb[3*n+1], Xz=xb[3*n+2];
  float Ax=xb[3*j], Ay=xb[3*j+1], Az=xb[3*j+2];
  float rx=Xx-Ax, ry=Xy-Ay, rz=Xz-Az;
  float rxy2=rx*rx+ry*ry;
  float rdis=sqrtf(rxy2+rz*rz);
  float ralpha=atan2f(ry,rx);
  float rbeta =atan2f(rz,sqrtf(rxy2));
  g_gdis[p*KK+k]=__expf(-rdis);

  float maxd=rdis, sx=Ax, sy=Ay, sz=Az;
#pragma unroll
  for(int m=1;m<16;m<<=1){
    maxd=fmaxf(maxd,__shfl_xor_sync(0xffffffffu,maxd,m));
    sx+=__shfl_xor_sync(0xffffffffu,sx,m);
    sy+=__shfl_xor_sync(0xffffffffu,sy,m);
    sz+=__shfl_xor_sync(0xffffffffu,sz,m);
  }
  float dvx=Xx-sx*0.0625f, dvy=Xy-sy*0.0625f, dvz=Xz-sz*0.0625f;
  float dalpha=atan2f(dvy,dvx);
  float dbeta =atan2f(dvz,sqrtf(dvx*dvx+dvy*dvy));
  if(k==0){
    float gn=sqrtf(Xx*Xx+Xy*Xy+Xz*Xz);
    g_lg[p]=(maxd*maxd*maxd)/(gn*gn*gn);
  }

  float lr[12]={ralpha-dalpha, rbeta-dbeta, rdis, Xx,Xy,Xz, Ax,Ay,Az, 0.f,0.f,0.f};
  float lo[16];
#pragma unroll
  for(int o=0;o<16;o++){
    float a=sLb[o];
#pragma unroll
    for(int q=0;q<3;q++){
      float4 w=*(const float4*)&sLW[o*12+4*q];
      a+=w.x*lr[4*q]+w.y*lr[4*q+1]+w.z*lr[4*q+2]+w.w*lr[4*q+3];
    }
    lo[o]=fmaxf(a,0.f);
  }
  float4* lp=(float4*)&g_lrep[((size_t)p*KK+k)*16];
  lp[0]=make_float4(lo[0],lo[1],lo[2],lo[3]);
  lp[1]=make_float4(lo[4],lo[5],lo[6],lo[7]);
  lp[2]=make_float4(lo[8],lo[9],lo[10],lo[11]);
  lp[3]=make_float4(lo[12],lo[13],lo[14],lo[15]);
}

// gather neighbor feature + fdis
__device__ __forceinline__ float fgather(const float* __restrict__ fjp,
                                         const float* __restrict__ fnp,
                                         float* fcat){
  const float4* fj4=(const float4*)fjp;
  const float4* fn4=(const float4*)fnp;
  float ad=0.f;
#pragma unroll
  for(int q=0;q<4;q++){
    float4 v=fj4[q], u=fn4[q];
    fcat[4*q]=v.x; fcat[4*q+1]=v.y; fcat[4*q+2]=v.z; fcat[4*q+3]=v.w;
    ad+=fabsf(u.x-v.x)+fabsf(u.y-v.y)+fabsf(u.z-v.z)+fabsf(u.w-v.w);
  }
  return __expf(-ad*0.0625f);
}

// ---------------- kernel B-pool: pool1 + p1m, 2 points per thread ---------
__global__ void __launch_bounds__(256,2) kBp(const int* __restrict__ nidx,
                                             const float* __restrict__ p1mb){
  __shared__ __align__(16) float sFC[1152];
  __shared__ __align__(16) float sPT[768];
  __shared__ float sPb[16];
  int t=threadIdx.x;
  for(int i=t;i<1152;i+=256) sFC[i]=g_p1fc[i];
  for(int i=t;i<768;i+=256)  sPT[i]=g_wp1mg[i];
  if(t<16) sPb[t]=p1mb[t];
  __syncthreads();

  int pp=t>>4, k=t&15;
  int pA=blockIdx.x*32+pp;
  int pB=pA+16;
  int bA=pA/NN, bB=pB/NN;
  int jA=nidx[pA*KK+k], jB=nidx[pB*KK+k];

  float fcatA[32], fcatB[32];
  // lrep -> channels 16..31 (both points)
  {
    const float4* la=(const float4*)&g_lrep[((size_t)pA*KK+k)*16];
    const float4* lb=(const float4*)&g_lrep[((size_t)pB*KK+k)*16];
#pragma unroll
    for(int q=0;q<4;q++){
      float4 v=la[q];
      fcatA[16+4*q]=v.x; fcatA[16+4*q+1]=v.y; fcatA[16+4*q+2]=v.z; fcatA[16+4*q+3]=v.w;
      float4 u=lb[q];
      fcatB[16+4*q]=u.x; fcatB[16+4*q+1]=u.y; fcatB[16+4*q+2]=u.z; fcatB[16+4*q+3]=u.w;
    }
  }
  float fdisA=fgather(&g_feat0[((size_t)bA*NN+jA)*16],&g_feat0[(size_t)pA*16],fcatA);
  float fdisB=fgather(&g_feat0[((size_t)bB*NN+jB)*16],&g_feat0[(size_t)pB*16],fcatB);
  float gdisA=g_gdis[pA*KK+k];
  float gdisB=g_gdis[pB*KK+k];

  float accA=0.f, accB=0.f;
#pragma unroll
  for(int blk=0;blk<4;blk++){
    float evA[8],tvA[8],evB[8],tvB[8];
#pragma unroll
    for(int o=0;o<8;o++){
      int ch=blk*8+o;
      const float* w=&sFC[ch*36];
      float2 wgf=*(const float2*)w;
      float s0=wgf.x*gdisA+wgf.y*fdisA;
      float s1=wgf.x*gdisB+wgf.y*fdisB;
#pragma unroll
      for(int q=0;q<8;q++){
        float4 wc=*(const float4*)(w+4+4*q);
        s0+=wc.x*fcatA[4*q]+wc.y*fcatA[4*q+1]+wc.z*fcatA[4*q+2]+wc.w*fcatA[4*q+3];
        s1+=wc.x*fcatB[4*q]+wc.y*fcatB[4*q+1]+wc.z*fcatB[4*q+2]+wc.w*fcatB[4*q+3];
      }
      float e0=__expf(s0), e1=__expf(s1);
      evA[o]=e0; tvA[o]=e0*fcatA[ch];
      evB[o]=e1; tvB[o]=e1*fcatB[ch];
    }
    // reduce-scatter over the 16-lane group
#pragma unroll
    for(int jj=0;jj<3;jj++){
      int m=1<<jj, half=4>>jj;
      bool hi=(k>>jj)&1;
#pragma unroll
      for(int i=0;i<half;i++){
        float sa=hi?evA[i]:evA[i+half];
        float ta=hi?tvA[i]:tvA[i+half];
        float sb2=hi?evB[i]:evB[i+half];
        float tb=hi?tvB[i]:tvB[i+half];
        float ra=__shfl_xor_sync(0xffffffffu,sa,m);
        float qa=__shfl_xor_sync(0xffffffffu,ta,m);
        float rb=__shfl_xor_sync(0xffffffffu,sb2,m);
        float qb=__shfl_xor_sync(0xffffffffu,tb,m);
        evA[i]=(hi?evA[i+half]:evA[i])+ra;
        tvA[i]=(hi?tvA[i+half]:tvA[i])+qa;
        evB[i]=(hi?evB[i+half]:evB[i])+rb;
        tvB[i]=(hi?tvB[i+half]:tvB[i])+qb;
      }
    }
    evA[0]+=__shfl_xor_sync(0xffffffffu,evA[0],8);
    tvA[0]+=__shfl_xor_sync(0xffffffffu,tvA[0],8);
    evB[0]+=__shfl_xor_sync(0xffffffffu,evB[0],8);
    tvB[0]+=__shfl_xor_sync(0xffffffffu,tvB[0],8);
    float gA[8], gB[8];
    gA[0]=__fdividef(tvA[0],evA[0]);
    gB[0]=__fdividef(tvB[0],evB[0]);
#pragma unroll
    for(int jj=0;jj<3;jj++){
      int m=1<<jj;
#pragma unroll
      for(int i=0;i<m;i++){
        gA[m+i]=__shfl_xor_sync(0xffffffffu,gA[i],m);
        gB[m+i]=__shfl_xor_sync(0xffffffffu,gB[i],m);
      }
    }
    const float* wg=&sPT[blk*192+k*12];
    float4 w0=*(const float4*)wg, w1=*(const float4*)(wg+4);
    accA+=w0.x*gA[0]+w0.y*gA[1]+w0.z*gA[2]+w0.w*gA[3]
         +w1.x*gA[4]+w1.y*gA[5]+w1.z*gA[6]+w1.w*gA[7];
    accB+=w0.x*gB[0]+w0.y*gB[1]+w0.z*gB[2]+w0.w*gB[3]
         +w1.x*gB[4]+w1.y*gB[5]+w1.z*gB[6]+w1.w*gB[7];
  }
  g_feat1[(size_t)pA*16+k]=fmaxf(accA+sPb[k],0.f);
  g_feat1[(size_t)pB*16+k]=fmaxf(accB+sPb[k],0.f);
}

// ---------------- kernel C1: pool-only, 2 points per thread ---------------
__global__ void __launch_bounds__(256,2) kC1(const int* __restrict__ nidx,
                    const float* __restrict__ lm2b, const float* __restrict__ p2mb){
  __shared__ __align__(16) float sL[256];
  __shared__ __align__(16) float sFC[1152];
  __shared__ __align__(16) float sPT[1280];
  __shared__ float sLb[16], sPb[32];
  int t=threadIdx.x;
  for(int i=t;i<256;i+=256)  sL[i]=g_wlm2[i];
  for(int i=t;i<1152;i+=256) sFC[i]=g_p2fc[i];
  for(int i=t;i<1280;i+=256) sPT[i]=g_wp2mg[i];
  if(t<16) sLb[t]=lm2b[t];
  if(t<32) sPb[t]=p2mb[t];
  __syncthreads();

  int pp=t>>4, k=t&15;
  int pA=blockIdx.x*32+pp;
  int pB=pA+16;
  int bA=pA/NN, bB=pB/NN;
  int jA=nidx[pA*KK+k], jB=nidx[pB*KK+k];

  float fcatA[32], fcatB[32];
  // lrep2 = relu(lm2 cbr(lrep)) for both points
  {
    float lrA[16], lrB[16];
    const float4* la=(const float4*)&g_lrep[((size_t)pA*KK+k)*16];
    const float4* lb=(const float4*)&g_lrep[((size_t)pB*KK+k)*16];
#pragma unroll
    for(int q=0;q<4;q++){
      float4 v=la[q]; lrA[4*q]=v.x; lrA[4*q+1]=v.y; lrA[4*q+2]=v.z; lrA[4*q+3]=v.w;
      float4 u=lb[q]; lrB[4*q]=u.x; lrB[4*q+1]=u.y; lrB[4*q+2]=u.z; lrB[4*q+3]=u.w;
    }
#pragma unroll
    for(int o=0;o<16;o++){
      float a0=sLb[o], a1=a0;
#pragma unroll
      for(int q=0;q<4;q++){
        float4 w=*(const float4*)&sL[o*16+4*q];
        a0+=w.x*lrA[4*q]+w.y*lrA[4*q+1]+w.z*lrA[4*q+2]+w.w*lrA[4*q+3];
        a1+=w.x*lrB[4*q]+w.y*lrB[4*q+1]+w.z*lrB[4*q+2]+w.w*lrB[4*q+3];
      }
      fcatA[16+o]=fmaxf(a0,0.f);
      fcatB[16+o]=fmaxf(a1,0.f);
    }
  }
  float fdisA=fgather(&g_feat1[((size_t)bA*NN+jA)*16],&g_feat1[(size_t)pA*16],fcatA);
  float fdisB=fgather(&g_feat1[((size_t)bB*NN+jB)*16],&g_feat1[(size_t)pB*16],fcatB);
  float gdisA=g_gdis[pA*KK+k];
  float gdisB=g_gdis[pB*KK+k];

  float v0A=0.f,v1A=0.f,v0B=0.f,v1B=0.f;
#pragma unroll
  for(int blk=0;blk<4;blk++){
    float evA[8],tvA[8],evB[8],tvB[8];
#pragma unroll
    for(int o=0;o<8;o++){
      int ch=blk*8+o;
      const float* w=&sFC[ch*36];
      float2 wgf=*(const float2*)w;
      float s0=wgf.x*gdisA+wgf.y*fdisA;
      float s1=wgf.x*gdisB+wgf.y*fdisB;
#pragma unroll
      for(int q=0;q<8;q++){
        float4 wc=*(const float4*)(w+4+4*q);
        s0+=wc.x*fcatA[4*q]+wc.y*fcatA[4*q+1]+wc.z*fcatA[4*q+2]+wc.w*fcatA[4*q+3];
        s1+=wc.x*fcatB[4*q]+wc.y*fcatB[4*q+1]+wc.z*fcatB[4*q+2]+wc.w*fcatB[4*q+3];
      }
      float e0=__expf(s0), e1=__expf(s1);
      evA[o]=e0; tvA[o]=e0*fcatA[ch];
      evB[o]=e1; tvB[o]=e1*fcatB[ch];
    }
#pragma unroll
    for(int jj=0;jj<3;jj++){
      int m=1<<jj, half=4>>jj;
      bool hi=(k>>jj)&1;
#pragma unroll
      for(int i=0;i<half;i++){
        float sa=hi?evA[i]:evA[i+half];
        float ta=hi?tvA[i]:tvA[i+half];
        float sb2=hi?evB[i]:evB[i+half];
        float tb=hi?tvB[i]:tvB[i+half];
        float ra=__shfl_xor_sync(0xffffffffu,sa,m);
        float qa=__shfl_xor_sync(0xffffffffu,ta,m);
        float rb=__shfl_xor_sync(0xffffffffu,sb2,m);
        float qb=__shfl_xor_sync(0xffffffffu,tb,m);
        evA[i]=(hi?evA[i+half]:evA[i])+ra;
        tvA[i]=(hi?tvA[i+half]:tvA[i])+qa;
        evB[i]=(hi?evB[i+half]:evB[i])+rb;
        tvB[i]=(hi?tvB[i+half]:tvB[i])+qb;
      }
    }
    evA[0]+=__shfl_xor_sync(0xffffffffu,evA[0],8);
    tvA[0]+=__shfl_xor_sync(0xffffffffu,tvA[0],8);
    evB[0]+=__shfl_xor_sync(0xffffffffu,evB[0],8);
    tvB[0]+=__shfl_xor_sync(0xffffffffu,tvB[0],8);
    float gA[8], gB[8];
    gA[0]=__fdividef(tvA[0],evA[0]);
    gB[0]=__fdividef(tvB[0],evB[0]);
#pragma unroll
    for(int jj=0;jj<3;jj++){
      int m=1<<jj;
#pragma unroll
      for(int i=0;i<m;i++){
        gA[m+i]=__shfl_xor_sync(0xffffffffu,gA[i],m);
        gB[m+i]=__shfl_xor_sync(0xffffffffu,gB[i],m);
      }
    }
    const float* wg=&sPT[blk*320+k*20];
#pragma unroll
    for(int i2=0;i2<4;i2++){
      float4 wv=*(const float4*)&wg[4*i2];   // {v0w,v1w} for channels 2*i2, 2*i2+1
      float ga=gA[2*i2], gb=gA[2*i2+1];
      v0A+=wv.x*ga+wv.z*gb; v1A+=wv.y*ga+wv.w*gb;
      float ha=gB[2*i2], hb=gB[2*i2+1];
      v0B+=wv.x*ha+wv.z*hb; v1B+=wv.y*ha+wv.w*hb;
    }
  }
  g_pool[(size_t)pA*32+k]   =fmaxf(v0A+sPb[k],0.f);
  g_pool[(size_t)pA*32+16+k]=fmaxf(v1A+sPb[k+16],0.f);
  g_pool[(size_t)pB*32+k]   =fmaxf(v0B+sPb[k],0.f);
  g_pool[(size_t)pB*32+16+k]=fmaxf(v1B+sPb[k+16],0.f);
}

// ---------------- kernel C2: fused m2+sc+m3 -> h -> m4 -> out -------------
__global__ void __launch_bounds__(256) kC2(const float* __restrict__ xyz,
                                           const float* __restrict__ m2b,
                                           const float* __restrict__ scb,
                                           const float* __restrict__ m3b,
                                           const float* __restrict__ m4b,
                                           float* __restrict__ out){
  __shared__ __align__(16) float sW[8192];
  __shared__ __align__(16) float sh[16*132];
  __shared__ __align__(16) float sv[16*32];
  __shared__ float sb[64], sM2b[64], sSCb[64], sM3b[64];
  int t=threadIdx.x;
  for(int i=t;i<8192;i+=256) sW[i]=g_m4t[i];
  if(t<64){ sb[t]=m4b[t]; sM2b[t]=m2b[t]; sSCb[t]=scb[t]; sM3b[t]=m3b[t]; }
  if(t<128){
    float4 v=((const float4*)&g_pool[(size_t)blockIdx.x*16*32])[t];
    ((float4*)sv)[t]=v;
  }
  __syncthreads();

  int pp=t>>4, k=t&15;
  int p=blockIdx.x*16+pp;
  int b=p/NN, n=p-b*NN;
  int o0=4*k;

  const float* vv=&sv[pp*32];
  float4 acc=make_float4(0.f,0.f,0.f,0.f);
#pragma unroll
  for(int c=0;c<32;c++){
    float vc=vv[c];
    float4 w=*(const float4*)&g_m2t[c*64+o0];
    acc.x+=w.x*vc; acc.y+=w.y*vc; acc.z+=w.z*vc; acc.w+=w.w*vc;
  }
  const float* ft=&g_featT[(size_t)p*16];
  float4 asc=make_float4(0.f,0.f,0.f,0.f);
#pragma unroll
  for(int c=0;c<16;c++){
    float fc=ft[c];
    float4 w=*(const float4*)&g_sct[c*64+o0];
    asc.x+=w.x*fc; asc.y+=w.y*fc; asc.z+=w.z*fc; asc.w+=w.w*fc;
  }
  const float* xb=xyz+(size_t)b*NN*3;
  float g3[4]={xb[3*n],xb[3*n+1],xb[3*n+2],g_lg[p]};
  float4 agc=make_float4(0.f,0.f,0.f,0.f);
#pragma unroll
  for(int c=0;c<4;c++){
    float fc=g3[c];
    float4 w=*(const float4*)&g_m3t[c*64+o0];
    agc.x+=w.x*fc; agc.y+=w.y*fc; agc.z+=w.z*fc; agc.w+=w.w*fc;
  }
  float4 hl=make_float4(acc.x+sM2b[o0]+asc.x+sSCb[o0],
                        acc.y+sM2b[o0+1]+asc.y+sSCb[o0+1],
                        acc.z+sM2b[o0+2]+asc.z+sSCb[o0+2],
                        acc.w+sM2b[o0+3]+asc.w+sSCb[o0+3]);
  float4 hh=make_float4(agc.x+sM3b[o0],agc.y+sM3b[o0+1],
                        agc.z+sM3b[o0+2],agc.w+sM3b[o0+3]);
  ((float4*)(sh+pp*132))[k]=hl;
  ((float4*)(sh+pp*132))[16+k]=hh;
  __syncthreads();

  const float4* hb4=(const float4*)&sh[pp*132];
  float4 a4=make_float4(0.f,0.f,0.f,0.f);
#pragma unroll
  for(int c4=0;c4<32;c4++){
    float4 h4=hb4[c4];
    float4 w0=*(const float4*)&sW[(4*c4  )*64+o0];
    float4 w1=*(const float4*)&sW[(4*c4+1)*64+o0];
    float4 w2=*(const float4*)&sW[(4*c4+2)*64+o0];
    float4 w3=*(const float4*)&sW[(4*c4+3)*64+o0];
    a4.x+=w0.x*h4.x+w1.x*h4.y+w2.x*h4.z+w3.x*h4.w;
    a4.y+=w0.y*h4.x+w1.y*h4.y+w2.y*h4.z+w3.y*h4.w;
    a4.z+=w0.z*h4.x+w1.z*h4.y+w2.z*h4.z+w3.z*h4.w;
    a4.w+=w0.w*h4.x+w1.w*h4.y+w2.w*h4.z+w3.w*h4.w;
  }
  size_t base=((size_t)b*64+o0)*NN+n;
  out[base]             =fmaxf(a4.x+sb[o0]  ,0.f);
  out[base+NN]          =fmaxf(a4.y+sb[o0+1],0.f);
  out[base+2*(size_t)NN]=fmaxf(a4.z+sb[o0+2],0.f);
  out[base+3*(size_t)NN]=fmaxf(a4.w+sb[o0+3],0.f);
}

// ---------------- launch ---------------------------------------------------
extern "C" void kernel_launch(void* const* d_in, const int* in_sizes, int n_in,
                              void* d_out, int out_size){
  const float* feature=(const float*)d_in[0];
  const float* xyz    =(const float*)d_in[1];
  const int*   nidx   =(const int*)  d_in[31];
  float* out=(float*)d_out;

  k_prep<<<1,256>>>((const float*)d_in[2],(const float*)d_in[3],
                    (const float*)d_in[5],(const float*)d_in[6],
                    (const float*)d_in[8],(const float*)d_in[9],
                    (const float*)d_in[11],
                    (const float*)d_in[12],(const float*)d_in[13],
                    (const float*)d_in[15],
                    (const float*)d_in[16],(const float*)d_in[17],
                    (const float*)d_in[19],(const float*)d_in[20],
                    (const float*)d_in[22],(const float*)d_in[23],
                    (const float*)d_in[25],(const float*)d_in[26],
                    (const float*)d_in[28],(const float*)d_in[29]);
  kA<<<NPTS/256,256>>>(feature,(const float*)d_in[4]);
  kBg<<<NPTS/16,256>>>(xyz,nidx,(const float*)d_in[7]);
  kBp<<<NPTS/32,256>>>(nidx,(const float*)d_in[14]);
  kC1<<<NPTS/32,256>>>(nidx,(const float*)d_in[10],(const float*)d_in[18]);
  kC2<<<NPTS/16,256>>>(xyz,(const float*)d_in[21],(const float*)d_in[24],
                       (const float*)d_in[27],(const float*)d_in[30],out);
}

// round 15
// speedup vs baseline: 1.3308x; 1.0897x over previous
#include <cuda_runtime.h>
#include <math.h>

#define BB 4
#define NN 20480
#define KK 16
#define NPTS (BB*NN)   // 81920

__host__ __device__ __forceinline__ int bitrev3(int x){
  return ((x&1)<<2)|(x&2)|((x&4)>>2);
}

// ---------------- scratch (device globals, no allocation) ----------------
__device__ float g_featT[NPTS*16];
__device__ float g_feat0[NPTS*16];
__device__ float g_feat1[NPTS*16];
__device__ float g_lrep[(size_t)NPTS*KK*16];
__device__ float g_gdis[NPTS*KK];
__device__ float g_lg[NPTS];
__device__ float g_pool[(size_t)NPTS*32];   // p2m output (32 ch per point)

// preprocessed weights
__device__ float g_wm1[256];
__device__ float g_wlm1p[192];
__device__ float g_wlm2[256];
__device__ float g_p1fc[1152];
__device__ float g_wp1mg[768];   // [blk4][k16][12] bit-reversed gather order (8 real)
__device__ float g_p2fc[1152];
__device__ float g_wp2mg[1280];  // [blk4][k16][20] float2 pairs (8 real)
__device__ float g_m2t[2048];   // [c][o] c<32 o<64
__device__ float g_sct[1024];   // [c][o] c<16
__device__ float g_m3t[256];    // [c][o] c<4
__device__ float g_m4t[8192];   // [c][o] c<128

// ---------------- prep ----------------------------------------------------
__global__ void k_prep(const float* m1W,const float* m1g,
                       const float* lm1W,const float* lm1g,
                       const float* lm2W,const float* lm2g,
                       const float* p1fcW,
                       const float* p1mW,const float* p1mg,
                       const float* p2fcW,
                       const float* p2mW,const float* p2mg,
                       const float* m2W,const float* m2g,
                       const float* scW,const float* scg,
                       const float* m3W,const float* m3g,
                       const float* m4W,const float* m4g)
{
  int t=threadIdx.x;
  for(int i=t;i<256;i+=256)  g_wm1[i]=m1g[i>>4]*m1W[i];
  for(int i=t;i<192;i+=256){
    int o=i/12,c=i%12;
    g_wlm1p[i]=(c<9)? lm1g[o]*lm1W[o*9+c] : 0.f;
  }
  for(int i=t;i<256;i+=256)  g_wlm2[i]=lm2g[i>>4]*lm2W[i];
  for(int i=t;i<1152;i+=256){
    int o=i/36,c=i%36; float v=0.f;
    if(c==0) v=p1fcW[o*34];
    else if(c==1) v=2.f*p1fcW[o*34+1];
    else if(c>=4) v=p1fcW[o*34+2+(c-4)];
    g_p1fc[i]=v;
  }
  // p1m weights, gather order: [blk][k][i<12] = g*W[k][blk*8+bitrev3((k^i)&7)], pad 4
  for(int i=t;i<768;i+=256){
    int blk=i/192, r=i%192, k=r/12, ii=r%12;
    float v=0.f;
    if(ii<8){ int c=blk*8+bitrev3((k^ii)&7); v=p1mg[k]*p1mW[k*32+c]; }
    g_wp1mg[i]=v;
  }
  for(int i=t;i<1152;i+=256){
    int o=i/36,c=i%36; float v=0.f;
    if(c==0) v=p2fcW[o*34];
    else if(c==1) v=2.f*p2fcW[o*34+1];
    else if(c>=4) v=p2fcW[o*34+2+(c-4)];
    g_p2fc[i]=v;
  }
  // p2m weights, gather order float2: [blk][k][i] = {g*W[k][c], g*W[k+16][c]}
  for(int i=t;i<640;i+=256){
    int blk=i/160, r=i%160, k=r/10, ii=r%10;
    float a=0.f,b=0.f;
    if(ii<8){
      int c=blk*8+bitrev3((k^ii)&7);
      a=p2mg[k]   *p2mW[k*32+c];
      b=p2mg[k+16]*p2mW[(k+16)*32+c];
    }
    g_wp2mg[2*i]=a; g_wp2mg[2*i+1]=b;
  }
  for(int i=t;i<2048;i+=256){int o=i>>5,c=i&31;  g_m2t[c*64+o]=m2g[o]*m2W[i];}
  for(int i=t;i<1024;i+=256){int o=i>>4,c=i&15;  g_sct[c*64+o]=scg[o]*scW[i];}
  for(int i=t;i<256;i+=256) {int o=i>>2,c=i&3;   g_m3t[c*64+o]=m3g[o]*m3W[i];}
  for(int i=t;i<8192;i+=256){int o=i>>7,c=i&127; g_m4t[c*64+o]=m4g[o]*m4W[i];}
}

// ---------------- kernel A ------------------------------------------------
__global__ void __launch_bounds__(256) kA(const float* __restrict__ feature,
                                          const float* __restrict__ m1b){
  __shared__ __align__(16) float sW[256];
  __shared__ float sb[16];
  int t=threadIdx.x;
  if(t<256) sW[t]=g_wm1[t];
  if(t<16)  sb[t]=m1b[t];
  __syncthreads();
  int p = blockIdx.x*256 + t;
  int b = p/NN, n = p - b*NN;
  float in[16];
  const float* fb = feature + (size_t)b*16*NN + n;
#pragma unroll
  for(int c=0;c<16;c++) in[c]=fb[(size_t)c*NN];
  float4* ft=(float4*)&g_featT[(size_t)p*16];
  ft[0]=make_float4(in[0],in[1],in[2],in[3]);
  ft[1]=make_float4(in[4],in[5],in[6],in[7]);
  ft[2]=make_float4(in[8],in[9],in[10],in[11]);
  ft[3]=make_float4(in[12],in[13],in[14],in[15]);
  float o0[16];
#pragma unroll
  for(int o=0;o<16;o++){
    float a=sb[o];
#pragma unroll
    for(int q=0;q<4;q++){
      float4 w=*(const float4*)&sW[o*16+4*q];
      a+=w.x*in[4*q]+w.y*in[4*q+1]+w.z*in[4*q+2]+w.w*in[4*q+3];
    }
    o0[o]=fmaxf(a,0.f);
  }
  float4* f0=(float4*)&g_feat0[(size_t)p*16];
  f0[0]=make_float4(o0[0],o0[1],o0[2],o0[3]);
  f0[1]=make_float4(o0[4],o0[5],o0[6],o0[7]);
  f0[2]=make_float4(o0[8],o0[9],o0[10],o0[11]);
  f0[3]=make_float4(o0[12],o0[13],o0[14],o0[15]);
}

// ---------------- kernel B-geom: geometry + lm1 -> lrep, gdis, lg ---------
__global__ void __launch_bounds__(256,3) kBg(const float* __restrict__ xyz,
                                             const int* __restrict__ nidx,
                                             const float* __restrict__ lm1b){
  __shared__ __align__(16) float sLW[192];
  __shared__ float sLb[16];
  int t=threadIdx.x;
  for(int i=t;i<192;i+=256) sLW[i]=g_wlm1p[i];
  if(t<16) sLb[t]=lm1b[t];
  __syncthreads();

  int pp=t>>4, k=t&15;
  int p = blockIdx.x*16 + pp;
  int b = p/NN, n = p - b*NN;
  int j = nidx[p*KK+k];
  const float* xb = xyz + (size_t)b*NN*3;
  float Xx=xb[3*n], Xy=xb[3*n+1], Xz=xb[3*n+2];
  float Ax=xb[3*j], Ay=xb[3*j+1], Az=xb[3*j+2];
  float rx=Xx-Ax, ry=Xy-Ay, rz=Xz-Az;
  float rxy2=rx*rx+ry*ry;
  float rdis=sqrtf(rxy2+rz*rz);
  float ralpha=atan2f(ry,rx);
  float rbeta =atan2f(rz,sqrtf(rxy2));
  g_gdis[p*KK+k]=__expf(-rdis);

  float maxd=rdis, sx=Ax, sy=Ay, sz=Az;
#pragma unroll
  for(int m=1;m<16;m<<=1){
    maxd=fmaxf(maxd,__shfl_xor_sync(0xffffffffu,maxd,m));
    sx+=__shfl_xor_sync(0xffffffffu,sx,m);
    sy+=__shfl_xor_sync(0xffffffffu,sy,m);
    sz+=__shfl_xor_sync(0xffffffffu,sz,m);
  }
  float dvx=Xx-sx*0.0625f, dvy=Xy-sy*0.0625f, dvz=Xz-sz*0.0625f;
  float dalpha=atan2f(dvy,dvx);
  float dbeta =atan2f(dvz,sqrtf(dvx*dvx+dvy*dvy));
  if(k==0){
    float gn=sqrtf(Xx*Xx+Xy*Xy+Xz*Xz);
    g_lg[p]=(maxd*maxd*maxd)/(gn*gn*gn);
  }

  float lr[12]={ralpha-dalpha, rbeta-dbeta, rdis, Xx,Xy,Xz, Ax,Ay,Az, 0.f,0.f,0.f};
  float lo[16];
#pragma unroll
  for(int o=0;o<16;o++){
    float a=sLb[o];
#pragma unroll
    for(int q=0;q<3;q++){
      float4 w=*(const float4*)&sLW[o*12+4*q];
      a+=w.x*lr[4*q]+w.y*lr[4*q+1]+w.z*lr[4*q+2]+w.w*lr[4*q+3];
    }
    lo[o]=fmaxf(a,0.f);
  }
  float4* lp=(float4*)&g_lrep[((size_t)p*KK+k)*16];
  lp[0]=make_float4(lo[0],lo[1],lo[2],lo[3]);
  lp[1]=make_float4(lo[4],lo[5],lo[6],lo[7]);
  lp[2]=make_float4(lo[8],lo[9],lo[10],lo[11]);
  lp[3]=make_float4(lo[12],lo[13],lo[14],lo[15]);
}

// gather neighbor feature + fdis
__device__ __forceinline__ float fgather(const float* __restrict__ fjp,
                                         const float* __restrict__ fnp,
                                         float* fcat){
  const float4* fj4=(const float4*)fjp;
  const float4* fn4=(const float4*)fnp;
  float ad=0.f;
#pragma unroll
  for(int q=0;q<4;q++){
    float4 v=fj4[q], u=fn4[q];
    fcat[4*q]=v.x; fcat[4*q+1]=v.y; fcat[4*q+2]=v.z; fcat[4*q+3]=v.w;
    ad+=fabsf(u.x-v.x)+fabsf(u.y-v.y)+fabsf(u.z-v.z)+fabsf(u.w-v.w);
  }
  return __expf(-ad*0.0625f);
}

// ---------------- kernel B-pool: pool1 + p1m, 2 points per thread ---------
__global__ void __launch_bounds__(256,2) kBp(const int* __restrict__ nidx,
                                             const float* __restrict__ p1mb){
  __shared__ __align__(16) float sFC[1152];
  __shared__ __align__(16) float sPT[768];
  __shared__ float sPb[16];
  int t=threadIdx.x;
  for(int i=t;i<1152;i+=256) sFC[i]=g_p1fc[i];
  for(int i=t;i<768;i+=256)  sPT[i]=g_wp1mg[i];
  if(t<16) sPb[t]=p1mb[t];
  __syncthreads();

  int pp=t>>4, k=t&15;
  int pA=blockIdx.x*32+pp;
  int pB=pA+16;
  int bA=pA/NN, bB=pB/NN;
  int jA=nidx[pA*KK+k], jB=nidx[pB*KK+k];

  float fcatA[32], fcatB[32];
  // lrep -> channels 16..31 (both points)
  {
    const float4* la=(const float4*)&g_lrep[((size_t)pA*KK+k)*16];
    const float4* lb=(const float4*)&g_lrep[((size_t)pB*KK+k)*16];
#pragma unroll
    for(int q=0;q<4;q++){
      float4 v=la[q];
      fcatA[16+4*q]=v.x; fcatA[16+4*q+1]=v.y; fcatA[16+4*q+2]=v.z; fcatA[16+4*q+3]=v.w;
      float4 u=lb[q];
      fcatB[16+4*q]=u.x; fcatB[16+4*q+1]=u.y; fcatB[16+4*q+2]=u.z; fcatB[16+4*q+3]=u.w;
    }
  }
  float fdisA=fgather(&g_feat0[((size_t)bA*NN+jA)*16],&g_feat0[(size_t)pA*16],fcatA);
  float fdisB=fgather(&g_feat0[((size_t)bB*NN+jB)*16],&g_feat0[(size_t)pB*16],fcatB);
  float gdisA=g_gdis[pA*KK+k];
  float gdisB=g_gdis[pB*KK+k];

  float accA=0.f, accB=0.f;
#pragma unroll
  for(int blk=0;blk<4;blk++){
    float evA[8],tvA[8],evB[8],tvB[8];
#pragma unroll
    for(int o=0;o<8;o++){
      int ch=blk*8+o;
      const float* w=&sFC[ch*36];
      float2 wgf=*(const float2*)w;
      float s0=wgf.x*gdisA+wgf.y*fdisA;
      float s1=wgf.x*gdisB+wgf.y*fdisB;
#pragma unroll
      for(int q=0;q<8;q++){
        float4 wc=*(const float4*)(w+4+4*q);
        s0+=wc.x*fcatA[4*q]+wc.y*fcatA[4*q+1]+wc.z*fcatA[4*q+2]+wc.w*fcatA[4*q+3];
        s1+=wc.x*fcatB[4*q]+wc.y*fcatB[4*q+1]+wc.z*fcatB[4*q+2]+wc.w*fcatB[4*q+3];
      }
      float e0=__expf(s0), e1=__expf(s1);
      evA[o]=e0; tvA[o]=e0*fcatA[ch];
      evB[o]=e1; tvB[o]=e1*fcatB[ch];
    }
    // reduce-scatter over the 16-lane group
#pragma unroll
    for(int jj=0;jj<3;jj++){
      int m=1<<jj, half=4>>jj;
      bool hi=(k>>jj)&1;
#pragma unroll
      for(int i=0;i<half;i++){
        float sa=hi?evA[i]:evA[i+half];
        float ta=hi?tvA[i]:tvA[i+half];
        float sb2=hi?evB[i]:evB[i+half];
        float tb=hi?tvB[i]:tvB[i+half];
        float ra=__shfl_xor_sync(0xffffffffu,sa,m);
        float qa=__shfl_xor_sync(0xffffffffu,ta,m);
        float rb=__shfl_xor_sync(0xffffffffu,sb2,m);
        float qb=__shfl_xor_sync(0xffffffffu,tb,m);
        evA[i]=(hi?evA[i+half]:evA[i])+ra;
        tvA[i]=(hi?tvA[i+half]:tvA[i])+qa;
        evB[i]=(hi?evB[i+half]:evB[i])+rb;
        tvB[i]=(hi?tvB[i+half]:tvB[i])+qb;
      }
    }
    evA[0]+=__shfl_xor_sync(0xffffffffu,evA[0],8);
    tvA[0]+=__shfl_xor_sync(0xffffffffu,tvA[0],8);
    evB[0]+=__shfl_xor_sync(0xffffffffu,evB[0],8);
    tvB[0]+=__shfl_xor_sync(0xffffffffu,tvB[0],8);
    float gA[8], gB[8];
    gA[0]=__fdividef(tvA[0],evA[0]);
    gB[0]=__fdividef(tvB[0],evB[0]);
#pragma unroll
    for(int jj=0;jj<3;jj++){
      int m=1<<jj;
#pragma unroll
      for(int i=0;i<m;i++){
        gA[m+i]=__shfl_xor_sync(0xffffffffu,gA[i],m);
        gB[m+i]=__shfl_xor_sync(0xffffffffu,gB[i],m);
      }
    }
    const float* wg=&sPT[blk*192+k*12];
    float4 w0=*(const float4*)wg, w1=*(const float4*)(wg+4);
    accA+=w0.x*gA[0]+w0.y*gA[1]+w0.z*gA[2]+w0.w*gA[3]
         +w1.x*gA[4]+w1.y*gA[5]+w1.z*gA[6]+w1.w*gA[7];
    accB+=w0.x*gB[0]+w0.y*gB[1]+w0.z*gB[2]+w0.w*gB[3]
         +w1.x*gB[4]+w1.y*gB[5]+w1.z*gB[6]+w1.w*gB[7];
  }
  g_feat1[(size_t)pA*16+k]=fmaxf(accA+sPb[k],0.f);
  g_feat1[(size_t)pB*16+k]=fmaxf(accB+sPb[k],0.f);
}

// ---------------- kernel C1: pool-only, 2 points per thread ---------------
__global__ void __launch_bounds__(256,2) kC1(const int* __restrict__ nidx,
                    const float* __restrict__ lm2b, const float* __restrict__ p2mb){
  __shared__ __align__(16) float sL[256];
  __shared__ __align__(16) float sFC[1152];
  __shared__ __align__(16) float sPT[1280];
  __shared__ float sLb[16], sPb[32];
  int t=threadIdx.x;
  for(int i=t;i<256;i+=256)  sL[i]=g_wlm2[i];
  for(int i=t;i<1152;i+=256) sFC[i]=g_p2fc[i];
  for(int i=t;i<1280;i+=256) sPT[i]=g_wp2mg[i];
  if(t<16) sLb[t]=lm2b[t];
  if(t<32) sPb[t]=p2mb[t];
  __syncthreads();

  int pp=t>>4, k=t&15;
  int pA=blockIdx.x*32+pp;
  int pB=pA+16;
  int bA=pA/NN, bB=pB/NN;
  int jA=nidx[pA*KK+k], jB=nidx[pB*KK+k];

  float fcatA[32], fcatB[32];
  // lrep2 = relu(lm2 cbr(lrep)) for both points
  {
    float lrA[16], lrB[16];
    const float4* la=(const float4*)&g_lrep[((size_t)pA*KK+k)*16];
    const float4* lb=(const float4*)&g_lrep[((size_t)pB*KK+k)*16];
#pragma unroll
    for(int q=0;q<4;q++){
      float4 v=la[q]; lrA[4*q]=v.x; lrA[4*q+1]=v.y; lrA[4*q+2]=v.z; lrA[4*q+3]=v.w;
      float4 u=lb[q]; lrB[4*q]=u.x; lrB[4*q+1]=u.y; lrB[4*q+2]=u.z; lrB[4*q+3]=u.w;
    }
#pragma unroll
    for(int o=0;o<16;o++){
      float a0=sLb[o], a1=a0;
#pragma unroll
      for(int q=0;q<4;q++){
        float4 w=*(const float4*)&sL[o*16+4*q];
        a0+=w.x*lrA[4*q]+w.y*lrA[4*q+1]+w.z*lrA[4*q+2]+w.w*lrA[4*q+3];
        a1+=w.x*lrB[4*q]+w.y*lrB[4*q+1]+w.z*lrB[4*q+2]+w.w*lrB[4*q+3];
      }
      fcatA[16+o]=fmaxf(a0,0.f);
      fcatB[16+o]=fmaxf(a1,0.f);
    }
  }
  float fdisA=fgather(&g_feat1[((size_t)bA*NN+jA)*16],&g_feat1[(size_t)pA*16],fcatA);
  float fdisB=fgather(&g_feat1[((size_t)bB*NN+jB)*16],&g_feat1[(size_t)pB*16],fcatB);
  float gdisA=g_gdis[pA*KK+k];
  float gdisB=g_gdis[pB*KK+k];

  float v0A=0.f,v1A=0.f,v0B=0.f,v1B=0.f;
#pragma unroll
  for(int blk=0;blk<4;blk++){
    float evA[8],tvA[8],evB[8],tvB[8];
#pragma unroll
    for(int o=0;o<8;o++){
      int ch=blk*8+o;
      const float* w=&sFC[ch*36];
      float2 wgf=*(const float2*)w;
      float s0=wgf.x*gdisA+wgf.y*fdisA;
      float s1=wgf.x*gdisB+wgf.y*fdisB;
#pragma unroll
      for(int q=0;q<8;q++){
        float4 wc=*(const float4*)(w+4+4*q);
        s0+=wc.x*fcatA[4*q]+wc.y*fcatA[4*q+1]+wc.z*fcatA[4*q+2]+wc.w*fcatA[4*q+3];
        s1+=wc.x*fcatB[4*q]+wc.y*fcatB[4*q+1]+wc.z*fcatB[4*q+2]+wc.w*fcatB[4*q+3];
      }
      float e0=__expf(s0), e1=__expf(s1);
      evA[o]=e0; tvA[o]=e0*fcatA[ch];
      evB[o]=e1; tvB[o]=e1*fcatB[ch];
    }
#pragma unroll
    for(int jj=0;jj<3;jj++){
      int m=1<<jj, half=4>>jj;
      bool hi=(k>>jj)&1;
#pragma unroll
      for(int i=0;i<half;i++){
        float sa=hi?evA[i]:evA[i+half];
        float ta=hi?tvA[i]:tvA[i+half];
        float sb2=hi?evB[i]:evB[i+half];
        float tb=hi?tvB[i]:tvB[i+half];
        float ra=__shfl_xor_sync(0xffffffffu,sa,m);
        float qa=__shfl_xor_sync(0xffffffffu,ta,m);
        float rb=__shfl_xor_sync(0xffffffffu,sb2,m);
        float qb=__shfl_xor_sync(0xffffffffu,tb,m);
        evA[i]=(hi?evA[i+half]:evA[i])+ra;
        tvA[i]=(hi?tvA[i+half]:tvA[i])+qa;
        evB[i]=(hi?evB[i+half]:evB[i])+rb;
        tvB[i]=(hi?tvB[i+half]:tvB[i])+qb;
      }
    }
    evA[0]+=__shfl_xor_sync(0xffffffffu,evA[0],8);
    tvA[0]+=__shfl_xor_sync(0xffffffffu,tvA[0],8);
    evB[0]+=__shfl_xor_sync(0xffffffffu,evB[0],8);
    tvB[0]+=__shfl_xor_sync(0xffffffffu,tvB[0],8);
    float gA[8], gB[8];
    gA[0]=__fdividef(tvA[0],evA[0]);
    gB[0]=__fdividef(tvB[0],evB[0]);
#pragma unroll
    for(int jj=0;jj<3;jj++){
      int m=1<<jj;
#pragma unroll
      for(int i=0;i<m;i++){
        gA[m+i]=__shfl_xor_sync(0xffffffffu,gA[i],m);
        gB[m+i]=__shfl_xor_sync(0xffffffffu,gB[i],m);
      }
    }
    const float* wg=&sPT[blk*320+k*20];
#pragma unroll
    for(int i2=0;i2<4;i2++){
      float4 wv=*(const float4*)&wg[4*i2];   // {v0w,v1w} for channels 2*i2, 2*i2+1
      float ga=gA[2*i2], gb=gA[2*i2+1];
      v0A+=wv.x*ga+wv.z*gb; v1A+=wv.y*ga+wv.w*gb;
      float ha=gB[2*i2], hb=gB[2*i2+1];
      v0B+=wv.x*ha+wv.z*hb; v1B+=wv.y*ha+wv.w*hb;
    }
  }
  g_pool[(size_t)pA*32+k]   =fmaxf(v0A+sPb[k],0.f);
  g_pool[(size_t)pA*32+16+k]=fmaxf(v1A+sPb[k+16],0.f);
  g_pool[(size_t)pB*32+k]   =fmaxf(v0B+sPb[k],0.f);
  g_pool[(size_t)pB*32+16+k]=fmaxf(v1B+sPb[k+16],0.f);
}

// ------- kernel C2: fused m2+sc+m3 -> h -> m4 -> out, 2 pts/thread --------
__global__ void __launch_bounds__(128) kC2(const float* __restrict__ xyz,
                                           const float* __restrict__ m2b,
                                           const float* __restrict__ scb,
                                           const float* __restrict__ m3b,
                                           const float* __restrict__ m4b,
                                           float* __restrict__ out){
  __shared__ __align__(16) float sW[8192];    // m4t
  __shared__ __align__(16) float sh[16*132];  // h staging (padded)
  __shared__ __align__(16) float sv[16*32];   // pooled vectors
  __shared__ float sb[64], sM2b[64], sSCb[64], sM3b[64];
  int t=threadIdx.x;
  for(int i=t;i<8192;i+=128) sW[i]=g_m4t[i];
  if(t<64){ sb[t]=m4b[t]; sM2b[t]=m2b[t]; sSCb[t]=scb[t]; sM3b[t]=m3b[t]; }
  {
    float4 v=((const float4*)&g_pool[(size_t)blockIdx.x*16*32])[t];
    ((float4*)sv)[t]=v;
  }
  __syncthreads();

  int pp=t>>4, k=t&15;      // pp in 0..7
  int pA=blockIdx.x*16+pp;  // two points per thread: pp and pp+8
  int pB=pA+8;
  int bA=pA/NN, nA=pA-bA*NN;
  int bB=pB/NN, nB=pB-bB*NN;
  int o0=4*k;

  // m2 (64x32): weight loaded once, FMA for both points
  const float* vA=&sv[pp*32];
  const float* vB=&sv[(pp+8)*32];
  float4 accA=make_float4(0.f,0.f,0.f,0.f);
  float4 accB=make_float4(0.f,0.f,0.f,0.f);
#pragma unroll
  for(int c=0;c<32;c++){
    float4 w=*(const float4*)&g_m2t[c*64+o0];
    float a=vA[c], b2=vB[c];
    accA.x+=w.x*a; accA.y+=w.y*a; accA.z+=w.z*a; accA.w+=w.w*a;
    accB.x+=w.x*b2; accB.y+=w.y*b2; accB.z+=w.z*b2; accB.w+=w.w*b2;
  }
  // sc (64x16) on raw feature
  const float* ftA=&g_featT[(size_t)pA*16];
  const float* ftB=&g_featT[(size_t)pB*16];
  float4 ascA=make_float4(0.f,0.f,0.f,0.f);
  float4 ascB=make_float4(0.f,0.f,0.f,0.f);
#pragma unroll
  for(int c=0;c<16;c++){
    float4 w=*(const float4*)&g_sct[c*64+o0];
    float a=ftA[c], b2=ftB[c];
    ascA.x+=w.x*a; ascA.y+=w.y*a; ascA.z+=w.z*a; ascA.w+=w.w*a;
    ascB.x+=w.x*b2; ascB.y+=w.y*b2; ascB.z+=w.z*b2; ascB.w+=w.w*b2;
  }
  // m3 (64x4)
  const float* xbA=xyz+(size_t)bA*NN*3;
  const float* xbB=xyz+(size_t)bB*NN*3;
  float g3A[4]={xbA[3*nA],xbA[3*nA+1],xbA[3*nA+2],g_lg[pA]};
  float g3B[4]={xbB[3*nB],xbB[3*nB+1],xbB[3*nB+2],g_lg[pB]};
  float4 agcA=make_float4(0.f,0.f,0.f,0.f);
  float4 agcB=make_float4(0.f,0.f,0.f,0.f);
#pragma unroll
  for(int c=0;c<4;c++){
    float4 w=*(const float4*)&g_m3t[c*64+o0];
    float a=g3A[c], b2=g3B[c];
    agcA.x+=w.x*a; agcA.y+=w.y*a; agcA.z+=w.z*a; agcA.w+=w.w*a;
    agcB.x+=w.x*b2; agcB.y+=w.y*b2; agcB.z+=w.z*b2; agcB.w+=w.w*b2;
  }
  float4 hlA=make_float4(accA.x+sM2b[o0]+ascA.x+sSCb[o0],
                         accA.y+sM2b[o0+1]+ascA.y+sSCb[o0+1],
                         accA.z+sM2b[o0+2]+ascA.z+sSCb[o0+2],
                         accA.w+sM2b[o0+3]+ascA.w+sSCb[o0+3]);
  float4 hhA=make_float4(agcA.x+sM3b[o0],agcA.y+sM3b[o0+1],
                         agcA.z+sM3b[o0+2],agcA.w+sM3b[o0+3]);
  float4 hlB=make_float4(accB.x+sM2b[o0]+ascB.x+sSCb[o0],
                         accB.y+sM2b[o0+1]+ascB.y+sSCb[o0+1],
                         accB.z+sM2b[o0+2]+ascB.z+sSCb[o0+2],
                         accB.w+sM2b[o0+3]+ascB.w+sSCb[o0+3]);
  float4 hhB=make_float4(agcB.x+sM3b[o0],agcB.y+sM3b[o0+1],
                         agcB.z+sM3b[o0+2],agcB.w+sM3b[o0+3]);
  ((float4*)(sh+pp*132))[k]=hlA;
  ((float4*)(sh+pp*132))[16+k]=hhA;
  ((float4*)(sh+(pp+8)*132))[k]=hlB;
  ((float4*)(sh+(pp+8)*132))[16+k]=hhB;
  __syncthreads();

  // m4 (64x128): weights loaded once, FMA for both points
  const float4* hA4=(const float4*)&sh[pp*132];
  const float4* hB4=(const float4*)&sh[(pp+8)*132];
  float4 a4A=make_float4(0.f,0.f,0.f,0.f);
  float4 a4B=make_float4(0.f,0.f,0.f,0.f);
#pragma unroll
  for(int c4=0;c4<32;c4++){
    float4 hA=hA4[c4];
    float4 hB=hB4[c4];
    float4 w0=*(const float4*)&sW[(4*c4  )*64+o0];
    float4 w1=*(const float4*)&sW[(4*c4+1)*64+o0];
    float4 w2=*(const float4*)&sW[(4*c4+2)*64+o0];
    float4 w3=*(const float4*)&sW[(4*c4+3)*64+o0];
    a4A.x+=w0.x*hA.x+w1.x*hA.y+w2.x*hA.z+w3.x*hA.w;
    a4A.y+=w0.y*hA.x+w1.y*hA.y+w2.y*hA.z+w3.y*hA.w;
    a4A.z+=w0.z*hA.x+w1.z*hA.y+w2.z*hA.z+w3.z*hA.w;
    a4A.w+=w0.w*hA.x+w1.w*hA.y+w2.w*hA.z+w3.w*hA.w;
    a4B.x+=w0.x*hB.x+w1.x*hB.y+w2.x*hB.z+w3.x*hB.w;
    a4B.y+=w0.y*hB.x+w1.y*hB.y+w2.y*hB.z+w3.y*hB.w;
    a4B.z+=w0.z*hB.x+w1.z*hB.y+w2.z*hB.z+w3.z*hB.w;
    a4B.w+=w0.w*hB.x+w1.w*hB.y+w2.w*hB.z+w3.w*hB.w;
  }
  size_t baseA=((size_t)bA*64+o0)*NN+nA;
  out[baseA]             =fmaxf(a4A.x+sb[o0]  ,0.f);
  out[baseA+NN]          =fmaxf(a4A.y+sb[o0+1],0.f);
  out[baseA+2*(size_t)NN]=fmaxf(a4A.z+sb[o0+2],0.f);
  out[baseA+3*(size_t)NN]=fmaxf(a4A.w+sb[o0+3],0.f);
  size_t baseB=((size_t)bB*64+o0)*NN+nB;
  out[baseB]             =fmaxf(a4B.x+sb[o0]  ,0.f);
  out[baseB+NN]          =fmaxf(a4B.y+sb[o0+1],0.f);
  out[baseB+2*(size_t)NN]=fmaxf(a4B.z+sb[o0+2],0.f);
  out[baseB+3*(size_t)NN]=fmaxf(a4B.w+sb[o0+3],0.f);
}

// ---------------- launch ---------------------------------------------------
extern "C" void kernel_launch(void* const* d_in, const int* in_sizes, int n_in,
                              void* d_out, int out_size){
  const float* feature=(const float*)d_in[0];
  const float* xyz    =(const float*)d_in[1];
  const int*   nidx   =(const int*)  d_in[31];
  float* out=(float*)d_out;

  k_prep<<<1,256>>>((const float*)d_in[2],(const float*)d_in[3],
                    (const float*)d_in[5],(const float*)d_in[6],
                    (const float*)d_in[8],(const float*)d_in[9],
                    (const float*)d_in[11],
                    (const float*)d_in[12],(const float*)d_in[13],
                    (const float*)d_in[15],
                    (const float*)d_in[16],(const float*)d_in[17],
                    (const float*)d_in[19],(const float*)d_in[20],
                    (const float*)d_in[22],(const float*)d_in[23],
                    (const float*)d_in[25],(const float*)d_in[26],
                    (const float*)d_in[28],(const float*)d_in[29]);
  kA<<<NPTS/256,256>>>(feature,(const float*)d_in[4]);
  kBg<<<NPTS/16,256>>>(xyz,nidx,(const float*)d_in[7]);
  kBp<<<NPTS/32,256>>>(nidx,(const float*)d_in[14]);
  kC1<<<NPTS/32,256>>>(nidx,(const float*)d_in[10],(const float*)d_in[18]);
  kC2<<<NPTS/16,128>>>(xyz,(const float*)d_in[21],(const float*)d_in[24],
                       (const float*)d_in[27],(const float*)d_in[30],out);
}